// round 1
// baseline (speedup 1.0000x reference)
#include <cuda_runtime.h>
#include <math.h>

// Problem dims
#define BSZ   16
#define LSEQ  1024
#define HDIM  256
#define PDIM  256
#define MROWS (BSZ*LSEQ)     // 16384
#define N1    (2*PDIM)       // 512  (re|im planes of Bu / states)
#define K1    HDIM           // 256
#define N3    HDIM           // 256
#define K3    (2*PDIM)       // 512
#define CHUNK 64
#define NCH   (LSEQ/CHUNK)   // 16

// Scratch (static device memory; no allocations allowed)
__device__ float g_S[(size_t)MROWS * N1];          // 32 MB: Bu then states, (M,512)
__device__ float g_Wb[K1 * N1];                     // (256,512): [Bbar_re^T | Bbar_im^T]
__device__ float g_Wc[K3 * N3];                     // (512,256): [2C_re ; -2C_im] (K-major)
__device__ float g_lam_re[PDIM], g_lam_im[PDIM];    // Lambda_bar
__device__ float g_lamT_re[PDIM], g_lamT_im[PDIM];  // Lambda_bar^CHUNK (exact, fp64)
__device__ float g_carry[BSZ * NCH * PDIM * 2];
__device__ float g_prefix[BSZ * NCH * PDIM * 2];

// ---------------------------------------------------------------------------
// Setup: discretization + weight repack.  fp64 for the transcendental math so
// lam^T phase (|Im| up to ~5000 rad) stays accurate; outputs cast to fp32.
// grid = (PDIM), block = (HDIM)
// ---------------------------------------------------------------------------
__global__ void s5_setup_kernel(const float* __restrict__ Lre,
                                const float* __restrict__ Lim,
                                const float* __restrict__ Bp,   // (P,H,2)
                                const float* __restrict__ Cp,   // (H,P,2)
                                const float* __restrict__ lstep) // (P,1)
{
    int p = blockIdx.x;
    int h = threadIdx.x;

    double lre = (double)Lre[p], lim = (double)Lim[p];
    double delta = exp((double)lstep[p]);
    double a = lre * delta, b = lim * delta;
    double ea = exp(a);
    double lam_r = ea * cos(b);
    double lam_i = ea * sin(b);
    // coef = (lam - 1) / Lambda
    double d2 = lre * lre + lim * lim;
    double nr = lam_r - 1.0, ni = lam_i;
    double cr = (nr * lre + ni * lim) / d2;
    double ci = (ni * lre - nr * lim) / d2;

    float br = Bp[((size_t)p * HDIM + h) * 2 + 0];
    float bi = Bp[((size_t)p * HDIM + h) * 2 + 1];
    g_Wb[h * N1 + p]        = (float)(cr * br - ci * bi);
    g_Wb[h * N1 + PDIM + p] = (float)(cr * bi + ci * br);

    float ccr = Cp[((size_t)h * PDIM + p) * 2 + 0];
    float cci = Cp[((size_t)h * PDIM + p) * 2 + 1];
    g_Wc[p * N3 + h]          =  2.0f * ccr;
    g_Wc[(PDIM + p) * N3 + h] = -2.0f * cci;

    if (h == 0) {
        g_lam_re[p] = (float)lam_r;
        g_lam_im[p] = (float)lam_i;
        double aT = a * CHUNK, bT = b * CHUNK;
        double eaT = exp(aT);
        g_lamT_re[p] = (float)(eaT * cos(bT));
        g_lamT_im[p] = (float)(eaT * sin(bT));
    }
}

// ---------------------------------------------------------------------------
// 128x128x8 register-blocked SGEMM, 256 threads, TM=TN=8, vectorized smem.
// FUSE=true adds the D*u feedthrough epilogue (GEMM3 -> d_out).
// ---------------------------------------------------------------------------
template <int KK, bool FUSE>
__global__ void __launch_bounds__(256, 2)
s5_gemm_kernel(const float* __restrict__ A,   // (M, KK) row-major
               const float* __restrict__ Bm,  // (KK, N) row-major
               float* __restrict__ Cm,        // (M, N)
               int N,
               const float* __restrict__ Dvec,
               const float* __restrict__ U)
{
    __shared__ float As[8][136];   // padded: conflict-free transposed stores
    __shared__ float Bs[8][128];

    const int t = threadIdx.x;
    const int arow = t >> 1, ac4 = (t & 1) * 4;
    const int brow = t >> 5, bc4 = (t & 31) * 4;
    const int ty = t >> 4, tx = t & 15;

    const int crow = blockIdx.y * 128;
    const int ccol = blockIdx.x * 128;

    const float* Ab = A + (size_t)(crow + arow) * KK + ac4;
    const float* Bb = Bm + (size_t)brow * N + ccol + bc4;

    float acc[8][8];
#pragma unroll
    for (int i = 0; i < 8; ++i)
#pragma unroll
        for (int j = 0; j < 8; ++j) acc[i][j] = 0.0f;

    for (int kt = 0; kt < KK; kt += 8) {
        float4 av = *(const float4*)(Ab + kt);
        float4 bv = *(const float4*)(Bb + (size_t)kt * N);
        As[ac4 + 0][arow] = av.x;
        As[ac4 + 1][arow] = av.y;
        As[ac4 + 2][arow] = av.z;
        As[ac4 + 3][arow] = av.w;
        *(float4*)&Bs[brow][bc4] = bv;
        __syncthreads();

#pragma unroll
        for (int k = 0; k < 8; ++k) {
            float4 m0 = *(const float4*)&As[k][ty * 8];
            float4 m1 = *(const float4*)&As[k][ty * 8 + 4];
            float4 n0 = *(const float4*)&Bs[k][tx * 8];
            float4 n1 = *(const float4*)&Bs[k][tx * 8 + 4];
            float rm[8] = {m0.x, m0.y, m0.z, m0.w, m1.x, m1.y, m1.z, m1.w};
            float rn[8] = {n0.x, n0.y, n0.z, n0.w, n1.x, n1.y, n1.z, n1.w};
#pragma unroll
            for (int i = 0; i < 8; ++i)
#pragma unroll
                for (int j = 0; j < 8; ++j)
                    acc[i][j] = fmaf(rm[i], rn[j], acc[i][j]);
        }
        __syncthreads();
    }

    // Epilogue
    float dreg[8];
    if (FUSE) {
#pragma unroll
        for (int j = 0; j < 8; ++j) dreg[j] = Dvec[ccol + tx * 8 + j];
    }
#pragma unroll
    for (int i = 0; i < 8; ++i) {
        int r = crow + ty * 8 + i;
        float* cp = Cm + (size_t)r * N + ccol + tx * 8;
        float v[8];
#pragma unroll
        for (int j = 0; j < 8; ++j) v[j] = acc[i][j];
        if (FUSE) {
            const float* up = U + (size_t)r * HDIM + ccol + tx * 8;
            float4 u0 = *(const float4*)(up);
            float4 u1 = *(const float4*)(up + 4);
            float uu[8] = {u0.x, u0.y, u0.z, u0.w, u1.x, u1.y, u1.z, u1.w};
#pragma unroll
            for (int j = 0; j < 8; ++j) v[j] = fmaf(dreg[j], uu[j], v[j]);
        }
        float4 s0 = {v[0], v[1], v[2], v[3]};
        float4 s1 = {v[4], v[5], v[6], v[7]};
        *(float4*)(cp) = s0;
        *(float4*)(cp + 4) = s1;
    }
}

// ---------------------------------------------------------------------------
// Chunked scan, phase A: per-(b,chunk,p) local recurrence -> carry (end state)
// grid = BSZ*NCH blocks, 256 threads (p)
// ---------------------------------------------------------------------------
__global__ void s5_scan_local_kernel()
{
    int b = blockIdx.x / NCH;
    int c = blockIdx.x % NCH;
    int p = threadIdx.x;
    float lr = g_lam_re[p], li = g_lam_im[p];
    const float* base = g_S + (size_t)(b * LSEQ + c * CHUNK) * N1;
    float xr = 0.f, xi = 0.f;
#pragma unroll 8
    for (int t = 0; t < CHUNK; ++t) {
        float sr = base[t * N1 + p];
        float si = base[t * N1 + PDIM + p];
        float nr = fmaf(lr, xr, fmaf(-li, xi, sr));
        float ni = fmaf(lr, xi, fmaf(li, xr, si));
        xr = nr; xi = ni;
    }
    int idx = ((b * NCH + c) * PDIM + p) * 2;
    g_carry[idx + 0] = xr;
    g_carry[idx + 1] = xi;
}

// Phase B: scan carries across chunks with multiplier lam^CHUNK (exclusive
// prefix = state entering each chunk).  grid = BSZ, 256 threads.
__global__ void s5_scan_carry_kernel()
{
    int b = blockIdx.x;
    int p = threadIdx.x;
    float lr = g_lamT_re[p], li = g_lamT_im[p];
    float xr = 0.f, xi = 0.f;
#pragma unroll
    for (int c = 0; c < NCH; ++c) {
        int idx = ((b * NCH + c) * PDIM + p) * 2;
        g_prefix[idx + 0] = xr;
        g_prefix[idx + 1] = xi;
        float cr = g_carry[idx + 0], ci = g_carry[idx + 1];
        float nr = fmaf(lr, xr, fmaf(-li, xi, cr));
        float ni = fmaf(lr, xi, fmaf(li, xr, ci));
        xr = nr; xi = ni;
    }
}

// Phase C: recompute local recurrence with correct carry-in, write states
// in place over Bu.  grid = BSZ*NCH, 256 threads.
__global__ void s5_scan_apply_kernel()
{
    int b = blockIdx.x / NCH;
    int c = blockIdx.x % NCH;
    int p = threadIdx.x;
    float lr = g_lam_re[p], li = g_lam_im[p];
    int idx = ((b * NCH + c) * PDIM + p) * 2;
    float xr = g_prefix[idx + 0];
    float xi = g_prefix[idx + 1];
    float* base = g_S + (size_t)(b * LSEQ + c * CHUNK) * N1;
#pragma unroll 4
    for (int t = 0; t < CHUNK; ++t) {
        float sr = base[t * N1 + p];
        float si = base[t * N1 + PDIM + p];
        float nr = fmaf(lr, xr, fmaf(-li, xi, sr));
        float ni = fmaf(lr, xi, fmaf(li, xr, si));
        xr = nr; xi = ni;
        base[t * N1 + p] = xr;
        base[t * N1 + PDIM + p] = xi;
    }
}

// ---------------------------------------------------------------------------
extern "C" void kernel_launch(void* const* d_in, const int* in_sizes, int n_in,
                              void* d_out, int out_size)
{
    const float* u    = (const float*)d_in[0];  // (16,1024,256)
    const float* Lre  = (const float*)d_in[1];  // (256,)
    const float* Lim  = (const float*)d_in[2];  // (256,)
    const float* Bp   = (const float*)d_in[3];  // (256,256,2)
    const float* Cp   = (const float*)d_in[4];  // (256,256,2)
    const float* Dv   = (const float*)d_in[5];  // (256,)
    const float* lst  = (const float*)d_in[6];  // (256,1)
    float* out = (float*)d_out;                 // (16,1024,256)

    float *sPtr, *wbPtr, *wcPtr;
    cudaGetSymbolAddress((void**)&sPtr,  g_S);
    cudaGetSymbolAddress((void**)&wbPtr, g_Wb);
    cudaGetSymbolAddress((void**)&wcPtr, g_Wc);

    // 1. discretize + repack weights
    s5_setup_kernel<<<PDIM, HDIM>>>(Lre, Lim, Bp, Cp, lst);

    // 2. Bu = u @ Wb   (16384x256 @ 256x512)
    {
        dim3 grid(N1 / 128, MROWS / 128);
        s5_gemm_kernel<K1, false><<<grid, 256>>>(u, wbPtr, sPtr, N1, nullptr, nullptr);
    }

    // 3. chunked complex scan over L (in place on g_S)
    s5_scan_local_kernel<<<BSZ * NCH, PDIM>>>();
    s5_scan_carry_kernel<<<BSZ, PDIM>>>();
    s5_scan_apply_kernel<<<BSZ * NCH, PDIM>>>();

    // 4. y = [x_re|x_im] @ [2C_re; -2C_im] + D*u   (16384x512 @ 512x256)
    {
        dim3 grid(N3 / 128, MROWS / 128);
        s5_gemm_kernel<K3, true><<<grid, 256>>>(sPtr, wcPtr, out, N3, Dv, u);
    }
}

// round 3
// speedup vs baseline: 2.0009x; 2.0009x over previous
#include <cuda_runtime.h>
#include <math.h>
#include <stdint.h>

// Problem dims
#define BSZ   16
#define LSEQ  1024
#define HDIM  256
#define PDIM  256
#define MROWS (BSZ*LSEQ)     // 16384
#define N1    (2*PDIM)       // 512  (re|im planes of Bu / states)
#define K1    HDIM           // 256
#define N3    HDIM           // 256
#define K3    (2*PDIM)       // 512
#define CHUNK 64
#define NCH   (LSEQ/CHUNK)   // 16

// Scratch (static device memory; no allocations allowed)
__device__ __align__(128) float g_S[(size_t)MROWS * N1];   // 32 MB: Bu then states
__device__ __align__(128) float g_Wb[N1 * K1];             // (512,256) N-major, K-contig
__device__ __align__(128) float g_Wc[N3 * K3];             // (256,512) N-major, K-contig
__device__ float g_lam_re[PDIM], g_lam_im[PDIM];           // Lambda_bar
__device__ float g_lamT_re[PDIM], g_lamT_im[PDIM];         // Lambda_bar^CHUNK (fp64-exact)
__device__ __align__(128) float g_carry[BSZ * NCH * PDIM * 2];
__device__ __align__(128) float g_prefix[BSZ * NCH * PDIM * 2];

// ---------------------------------------------------------------------------
// tf32 helpers (legacy mma.sync path — no sm_103a-only instructions)
// ---------------------------------------------------------------------------
__device__ __forceinline__ uint32_t f2tf32(float f) {
    uint32_t r;
    asm("cvt.rna.tf32.f32 %0, %1;" : "=r"(r) : "f"(f));
    return r;
}

__device__ __forceinline__ void mma16n8k8(float c[4], const uint32_t a[4],
                                          const uint32_t b[2]) {
    asm volatile(
        "mma.sync.aligned.m16n8k8.row.col.f32.tf32.tf32.f32 "
        "{%0,%1,%2,%3}, {%4,%5,%6,%7}, {%8,%9}, {%0,%1,%2,%3};"
        : "+f"(c[0]), "+f"(c[1]), "+f"(c[2]), "+f"(c[3])
        : "r"(a[0]), "r"(a[1]), "r"(a[2]), "r"(a[3]), "r"(b[0]), "r"(b[1]));
}

// ---------------------------------------------------------------------------
// Setup: discretization + weight repack (N-major, K-contiguous for B operand).
// grid = (PDIM), block = (HDIM)
// ---------------------------------------------------------------------------
__global__ void s5_setup_kernel(const float* __restrict__ Lre,
                                const float* __restrict__ Lim,
                                const float* __restrict__ Bp,    // (P,H,2)
                                const float* __restrict__ Cp,    // (H,P,2)
                                const float* __restrict__ lstep) // (P,1)
{
    int p = blockIdx.x;
    int h = threadIdx.x;

    double lre = (double)Lre[p], lim = (double)Lim[p];
    double delta = exp((double)lstep[p]);
    double a = lre * delta, b = lim * delta;
    double ea = exp(a);
    double lam_r = ea * cos(b);
    double lam_i = ea * sin(b);
    double d2 = lre * lre + lim * lim;
    double nr = lam_r - 1.0, ni = lam_i;
    double cr = (nr * lre + ni * lim) / d2;
    double ci = (ni * lre - nr * lim) / d2;

    float br = Bp[((size_t)p * HDIM + h) * 2 + 0];
    float bi = Bp[((size_t)p * HDIM + h) * 2 + 1];
    g_Wb[(size_t)p * K1 + h]          = (float)(cr * br - ci * bi);
    g_Wb[(size_t)(PDIM + p) * K1 + h] = (float)(cr * bi + ci * br);

    float ccr = Cp[((size_t)h * PDIM + p) * 2 + 0];
    float cci = Cp[((size_t)h * PDIM + p) * 2 + 1];
    g_Wc[(size_t)h * K3 + p]        =  2.0f * ccr;
    g_Wc[(size_t)h * K3 + PDIM + p] = -2.0f * cci;

    if (h == 0) {
        g_lam_re[p] = (float)lam_r;
        g_lam_im[p] = (float)lam_i;
        double aT = a * CHUNK, bT = b * CHUNK;
        double eaT = exp(aT);
        g_lamT_re[p] = (float)(eaT * cos(bT));
        g_lamT_im[p] = (float)(eaT * sin(bT));
    }
}

// ---------------------------------------------------------------------------
// tf32 mma.sync GEMM: C[M,NTOT] = A[M,KK] * B[NTOT,KK]^T (B is N-major).
// 128x128 block tile, 8 warps (4m x 2n), warp tile 32x64, k-step 16,
// double-buffered SMEM with tf32 conversion at the store.
// FUSE adds the D*u feedthrough epilogue.
// SMEM layout [k][m] with row pad 8 floats (136): fragment LDS banks are
// (8k+m)%32 -> conflict-free across a warp.
// ---------------------------------------------------------------------------
template <int KK, int NTOT, bool FUSE>
__global__ void __launch_bounds__(256, 2)
s5_mma_gemm(const float* __restrict__ A,
            const float* __restrict__ B,
            float* __restrict__ C,
            const float* __restrict__ Dvec,
            const float* __restrict__ U)
{
    __shared__ float As[2][16][136];
    __shared__ float Bs[2][16][136];

    const int t = threadIdx.x;
    const int lane = t & 31, w = t >> 5;
    const int g = lane >> 2, tig = lane & 3;
    const int mBase = (w & 3) * 32;   // warp m-offset
    const int nBase = (w >> 2) * 64;  // warp n-offset
    const int m0 = blockIdx.y * 128, n0 = blockIdx.x * 128;

    const int ldRow = t >> 1;         // 0..127
    const int ldKh  = (t & 1) * 8;    // 0 or 8
    const float* Arow = A + (size_t)(m0 + ldRow) * KK + ldKh;
    const float* Brow = B + (size_t)(n0 + ldRow) * KK + ldKh;

    const int NIT = KK / 16;

    float acc[2][8][4];
#pragma unroll
    for (int mi = 0; mi < 2; ++mi)
#pragma unroll
        for (int ni = 0; ni < 8; ++ni)
#pragma unroll
            for (int q = 0; q < 4; ++q) acc[mi][ni][q] = 0.0f;

    float4 av0, av1, bv0, bv1;
    // prologue: tile 0
    av0 = *(const float4*)(Arow);
    av1 = *(const float4*)(Arow + 4);
    bv0 = *(const float4*)(Brow);
    bv1 = *(const float4*)(Brow + 4);
#pragma unroll
    for (int j = 0; j < 4; ++j) {
        As[0][ldKh + j][ldRow]     = __uint_as_float(f2tf32(((const float*)&av0)[j]));
        As[0][ldKh + 4 + j][ldRow] = __uint_as_float(f2tf32(((const float*)&av1)[j]));
        Bs[0][ldKh + j][ldRow]     = __uint_as_float(f2tf32(((const float*)&bv0)[j]));
        Bs[0][ldKh + 4 + j][ldRow] = __uint_as_float(f2tf32(((const float*)&bv1)[j]));
    }
    __syncthreads();

    for (int it = 0; it < NIT; ++it) {
        const int buf = it & 1;
        const bool hasNext = (it + 1) < NIT;
        if (hasNext) {
            const float* An = Arow + (it + 1) * 16;
            const float* Bn = Brow + (it + 1) * 16;
            av0 = *(const float4*)(An);
            av1 = *(const float4*)(An + 4);
            bv0 = *(const float4*)(Bn);
            bv1 = *(const float4*)(Bn + 4);
        }

#pragma unroll
        for (int kk = 0; kk < 16; kk += 8) {
            uint32_t afr[2][4], bfr[8][2];
#pragma unroll
            for (int mi = 0; mi < 2; ++mi) {
                int m = mBase + mi * 16 + g;
                afr[mi][0] = __float_as_uint(As[buf][kk + tig][m]);
                afr[mi][1] = __float_as_uint(As[buf][kk + tig][m + 8]);
                afr[mi][2] = __float_as_uint(As[buf][kk + tig + 4][m]);
                afr[mi][3] = __float_as_uint(As[buf][kk + tig + 4][m + 8]);
            }
#pragma unroll
            for (int ni = 0; ni < 8; ++ni) {
                int n = nBase + ni * 8 + g;
                bfr[ni][0] = __float_as_uint(Bs[buf][kk + tig][n]);
                bfr[ni][1] = __float_as_uint(Bs[buf][kk + tig + 4][n]);
            }
#pragma unroll
            for (int mi = 0; mi < 2; ++mi)
#pragma unroll
                for (int ni = 0; ni < 8; ++ni)
                    mma16n8k8(acc[mi][ni], afr[mi], bfr[ni]);
        }

        if (hasNext) {
            const int nb = buf ^ 1;
#pragma unroll
            for (int j = 0; j < 4; ++j) {
                As[nb][ldKh + j][ldRow]     = __uint_as_float(f2tf32(((const float*)&av0)[j]));
                As[nb][ldKh + 4 + j][ldRow] = __uint_as_float(f2tf32(((const float*)&av1)[j]));
                Bs[nb][ldKh + j][ldRow]     = __uint_as_float(f2tf32(((const float*)&bv0)[j]));
                Bs[nb][ldKh + 4 + j][ldRow] = __uint_as_float(f2tf32(((const float*)&bv1)[j]));
            }
            __syncthreads();
        }
    }

    // Epilogue: c fragment rows g / g+8, cols 2*tig, 2*tig+1 (float2 stores)
#pragma unroll
    for (int mi = 0; mi < 2; ++mi) {
        int row0 = m0 + mBase + mi * 16 + g;
#pragma unroll
        for (int ni = 0; ni < 8; ++ni) {
            int col = n0 + nBase + ni * 8 + 2 * tig;
            float2 v0 = make_float2(acc[mi][ni][0], acc[mi][ni][1]);
            float2 v1 = make_float2(acc[mi][ni][2], acc[mi][ni][3]);
            if (FUSE) {
                float d0 = Dvec[col], d1 = Dvec[col + 1];
                float2 u0 = *(const float2*)(U + (size_t)row0 * HDIM + col);
                float2 u1 = *(const float2*)(U + (size_t)(row0 + 8) * HDIM + col);
                v0.x = fmaf(d0, u0.x, v0.x); v0.y = fmaf(d1, u0.y, v0.y);
                v1.x = fmaf(d0, u1.x, v1.x); v1.y = fmaf(d1, u1.y, v1.y);
            }
            *(float2*)(C + (size_t)row0 * NTOT + col) = v0;
            *(float2*)(C + (size_t)(row0 + 8) * NTOT + col) = v1;
        }
    }
}

// ---------------------------------------------------------------------------
// Chunked scan, phase A: per-(b,chunk,p) local recurrence -> carry
// ---------------------------------------------------------------------------
__global__ void s5_scan_local_kernel()
{
    int b = blockIdx.x / NCH;
    int c = blockIdx.x % NCH;
    int p = threadIdx.x;
    float lr = g_lam_re[p], li = g_lam_im[p];
    const float* base = g_S + (size_t)(b * LSEQ + c * CHUNK) * N1;
    float xr = 0.f, xi = 0.f;
#pragma unroll 8
    for (int t = 0; t < CHUNK; ++t) {
        float sr = base[t * N1 + p];
        float si = base[t * N1 + PDIM + p];
        float nr = fmaf(lr, xr, fmaf(-li, xi, sr));
        float ni = fmaf(lr, xi, fmaf(li, xr, si));
        xr = nr; xi = ni;
    }
    int idx = ((b * NCH + c) * PDIM + p) * 2;
    g_carry[idx + 0] = xr;
    g_carry[idx + 1] = xi;
}

// Phase B: preload all carries (MLP), then serial scan with lam^CHUNK.
__global__ void s5_scan_carry_kernel()
{
    int b = blockIdx.x;
    int p = threadIdx.x;
    float lr = g_lamT_re[p], li = g_lamT_im[p];
    float cr[NCH], ci[NCH];
#pragma unroll
    for (int c = 0; c < NCH; ++c) {
        int idx = ((b * NCH + c) * PDIM + p) * 2;
        cr[c] = g_carry[idx + 0];
        ci[c] = g_carry[idx + 1];
    }
    float xr = 0.f, xi = 0.f;
#pragma unroll
    for (int c = 0; c < NCH; ++c) {
        int idx = ((b * NCH + c) * PDIM + p) * 2;
        g_prefix[idx + 0] = xr;
        g_prefix[idx + 1] = xi;
        float nr = fmaf(lr, xr, fmaf(-li, xi, cr[c]));
        float ni = fmaf(lr, xi, fmaf(li, xr, ci[c]));
        xr = nr; xi = ni;
    }
}

// Phase C: apply prefixes, rewrite states in place.
__global__ void s5_scan_apply_kernel()
{
    int b = blockIdx.x / NCH;
    int c = blockIdx.x % NCH;
    int p = threadIdx.x;
    float lr = g_lam_re[p], li = g_lam_im[p];
    int idx = ((b * NCH + c) * PDIM + p) * 2;
    float xr = g_prefix[idx + 0];
    float xi = g_prefix[idx + 1];
    float* base = g_S + (size_t)(b * LSEQ + c * CHUNK) * N1;
#pragma unroll 4
    for (int t = 0; t < CHUNK; ++t) {
        float sr = base[t * N1 + p];
        float si = base[t * N1 + PDIM + p];
        float nr = fmaf(lr, xr, fmaf(-li, xi, sr));
        float ni = fmaf(lr, xi, fmaf(li, xr, si));
        xr = nr; xi = ni;
        base[t * N1 + p] = xr;
        base[t * N1 + PDIM + p] = xi;
    }
}

// ---------------------------------------------------------------------------
extern "C" void kernel_launch(void* const* d_in, const int* in_sizes, int n_in,
                              void* d_out, int out_size)
{
    const float* u   = (const float*)d_in[0];  // (16,1024,256)
    const float* Lre = (const float*)d_in[1];
    const float* Lim = (const float*)d_in[2];
    const float* Bp  = (const float*)d_in[3];  // (256,256,2)
    const float* Cp  = (const float*)d_in[4];  // (256,256,2)
    const float* Dv  = (const float*)d_in[5];  // (256,)
    const float* lst = (const float*)d_in[6];  // (256,1)
    float* out = (float*)d_out;                // (16,1024,256)

    float *sPtr, *wbPtr, *wcPtr;
    cudaGetSymbolAddress((void**)&sPtr,  g_S);
    cudaGetSymbolAddress((void**)&wbPtr, g_Wb);
    cudaGetSymbolAddress((void**)&wcPtr, g_Wc);

    // 1. discretize + repack weights
    s5_setup_kernel<<<PDIM, HDIM>>>(Lre, Lim, Bp, Cp, lst);

    // 2. Bu = u @ Wb^T   (16384x256 @ (512x256)^T), tf32 tensor path
    s5_mma_gemm<K1, N1, false><<<dim3(N1 / 128, MROWS / 128), 256>>>(
        u, wbPtr, sPtr, nullptr, nullptr);

    // 3. chunked complex scan over L (in place on g_S)
    s5_scan_local_kernel<<<BSZ * NCH, PDIM>>>();
    s5_scan_carry_kernel<<<BSZ, PDIM>>>();
    s5_scan_apply_kernel<<<BSZ * NCH, PDIM>>>();

    // 4. y = states @ Wc^T + D*u   (16384x512 @ (256x512)^T), tf32 + fused epilogue
    s5_mma_gemm<K3, N3, true><<<dim3(N3 / 128, MROWS / 128), 256>>>(
        sPtr, wcPtr, out, Dv, u);
}

// round 5
// speedup vs baseline: 2.4899x; 1.2444x over previous
#include <cuda_runtime.h>
#include <cuda_fp16.h>
#include <math.h>
#include <stdint.h>

// Problem dims
#define BSZ   16
#define LSEQ  1024
#define HDIM  256
#define PDIM  256
#define MROWS (BSZ*LSEQ)     // 16384
#define N1    (2*PDIM)       // 512  (re|im planes of Bu / states)
#define K1    HDIM           // 256
#define N3    HDIM           // 256
#define K3    (2*PDIM)       // 512
#define CHUNK 64
#define NCH   (LSEQ/CHUNK)   // 16

// Scratch (static device memory; no allocations allowed)
__device__ __align__(128) float g_S[(size_t)MROWS * N1];   // 32 MB: Bu then states
__device__ __align__(128) float g_Wb[N1 * K1];             // (512,256) N-major, K-contig
__device__ __align__(128) float g_Wc[N3 * K3];             // (256,512) N-major, K-contig
__device__ float g_lam_re[PDIM], g_lam_im[PDIM];           // Lambda_bar
__device__ float g_powT_re[NCH][PDIM], g_powT_im[NCH][PDIM]; // Lambda_bar^(CHUNK*j), fp64-exact
__device__ float g_inv_scl[PDIM];                          // 2^e unscale factors
__device__ __align__(128) float g_car_re[BSZ * NCH * PDIM];
__device__ __align__(128) float g_car_im[BSZ * NCH * PDIM];

// ---------------------------------------------------------------------------
// helpers
// ---------------------------------------------------------------------------
__device__ __forceinline__ uint32_t smem_u32(const void* p) {
    uint32_t a;
    asm("{ .reg .u64 t; cvta.to.shared.u64 t, %1; cvt.u32.u64 %0, t; }" : "=r"(a) : "l"(p));
    return a;
}
// pack two fp32 -> fp16x2 (lo = a, hi = b)
__device__ __forceinline__ uint32_t f2h2(float a, float b) {
    uint32_t r;
    asm("cvt.rn.f16x2.f32 %0, %1, %2;" : "=r"(r) : "f"(b), "f"(a));
    return r;
}
__device__ __forceinline__ void ldsm4(uint32_t& r0, uint32_t& r1, uint32_t& r2,
                                      uint32_t& r3, uint32_t addr) {
    asm volatile("ldmatrix.sync.aligned.m8n8.x4.shared.b16 {%0,%1,%2,%3}, [%4];"
                 : "=r"(r0), "=r"(r1), "=r"(r2), "=r"(r3) : "r"(addr));
}
__device__ __forceinline__ void mma16816(float c[4], const uint32_t a[4],
                                         uint32_t b0, uint32_t b1) {
    asm volatile(
        "mma.sync.aligned.m16n8k16.row.col.f32.f16.f16.f32 "
        "{%0,%1,%2,%3}, {%4,%5,%6,%7}, {%8,%9}, {%0,%1,%2,%3};"
        : "+f"(c[0]), "+f"(c[1]), "+f"(c[2]), "+f"(c[3])
        : "r"(a[0]), "r"(a[1]), "r"(a[2]), "r"(a[3]), "r"(b0), "r"(b1));
}

// ---------------------------------------------------------------------------
// Setup: discretization + weight repack (N-major, K-contiguous for B operand)
// + lamT power table + per-row power-of-2 scaling to keep Wb out of fp16
// subnormal range.  grid = PDIM, block = HDIM.
// ---------------------------------------------------------------------------
__global__ void s5_setup_kernel(const float* __restrict__ Lre,
                                const float* __restrict__ Lim,
                                const float* __restrict__ Bp,    // (P,H,2)
                                const float* __restrict__ Cp,    // (H,P,2)
                                const float* __restrict__ lstep) // (P,1)
{
    int p = blockIdx.x;
    int h = threadIdx.x;

    double lre = (double)Lre[p], lim = (double)Lim[p];
    double delta = exp((double)lstep[p]);
    double a = lre * delta, b = lim * delta;
    double ea = exp(a);
    double lam_r = ea * cos(b);
    double lam_i = ea * sin(b);
    double d2 = lre * lre + lim * lim;
    double nr = lam_r - 1.0, ni = lam_i;
    double cr = (nr * lre + ni * lim) / d2;
    double ci = (ni * lre - nr * lim) / d2;

    // power-of-2 prescale: |coef|*scl in [0.5, 1)
    int e;
    frexp(sqrt(cr * cr + ci * ci), &e);
    double scl = ldexp(1.0, -e);
    cr *= scl; ci *= scl;

    float br = Bp[((size_t)p * HDIM + h) * 2 + 0];
    float bi = Bp[((size_t)p * HDIM + h) * 2 + 1];
    g_Wb[(size_t)p * K1 + h]          = (float)(cr * br - ci * bi);
    g_Wb[(size_t)(PDIM + p) * K1 + h] = (float)(cr * bi + ci * br);

    float ccr = Cp[((size_t)h * PDIM + p) * 2 + 0];
    float cci = Cp[((size_t)h * PDIM + p) * 2 + 1];
    g_Wc[(size_t)h * K3 + p]        =  2.0f * ccr;
    g_Wc[(size_t)h * K3 + PDIM + p] = -2.0f * cci;

    if (h == 0) {
        g_lam_re[p] = (float)lam_r;
        g_lam_im[p] = (float)lam_i;
        g_inv_scl[p] = (float)ldexp(1.0, e);   // exact inverse
    }
    if (h < NCH) {   // lamT^h = exp(Lambda*Delta*CHUNK*h), closed form in fp64
        double aT = a * CHUNK * h, bT = b * CHUNK * h;
        double eaT = exp(aT);
        g_powT_re[h][p] = (float)(eaT * cos(bT));
        g_powT_im[h][p] = (float)(eaT * sin(bT));
    }
}

// ---------------------------------------------------------------------------
// fp16 mma.sync GEMM: C[M,NTOT] = A[M,KK] * B[NTOT,KK]^T (B is N-major).
// 128x128 block tile, 8 warps (4m x 2n), warp tile 32x64, k-chunk 32,
// double-buffered SMEM (fp16, XOR-swizzled 16B chunks), ldmatrix fragments
// (non-trans for BOTH operands: K-contiguous rows give k-consecutive pairs).
// FUSE adds the D*u feedthrough epilogue.
// ---------------------------------------------------------------------------
template <int KK, int NTOT, bool FUSE>
__global__ void __launch_bounds__(256, 2)
s5_mma_gemm(const float* __restrict__ A,
            const float* __restrict__ B,
            float* __restrict__ C,
            const float* __restrict__ Dvec,
            const float* __restrict__ U)
{
    __shared__ uint4 As[2][128][4];
    __shared__ uint4 Bs[2][128][4];

    const int t = threadIdx.x;
    const int lane = t & 31, w = t >> 5;
    const int g = lane >> 2, tig = lane & 3;
    const int mBase = (w & 3) * 32;
    const int nBase = (w >> 2) * 64;
    const int m0 = blockIdx.y * 128, n0 = blockIdx.x * 128;

    const int r  = t >> 1;           // staging row 0..127
    const int kh = (t & 1) * 16;     // k offset within chunk-of-32
    const int cbs = (t & 1) * 2;     // 16B-chunk base (0 or 2)
    const int swz = (r >> 1) & 3;

    const float* Ag = A + (size_t)(m0 + r) * KK + kh;
    const float* Bg = B + (size_t)(n0 + r) * KK + kh;

    const int NIT = KK / 32;

    float acc[2][8][4];
#pragma unroll
    for (int mi = 0; mi < 2; ++mi)
#pragma unroll
        for (int ni = 0; ni < 8; ++ni)
#pragma unroll
            for (int q = 0; q < 4; ++q) acc[mi][ni][q] = 0.0f;

    // stage chunk 0
    {
        float4 a0 = *(const float4*)(Ag),     a1 = *(const float4*)(Ag + 4);
        float4 a2 = *(const float4*)(Ag + 8), a3 = *(const float4*)(Ag + 12);
        float4 b0 = *(const float4*)(Bg),     b1 = *(const float4*)(Bg + 4);
        float4 b2 = *(const float4*)(Bg + 8), b3 = *(const float4*)(Bg + 12);
        As[0][r][(cbs + 0) ^ swz] = make_uint4(f2h2(a0.x,a0.y), f2h2(a0.z,a0.w),
                                               f2h2(a1.x,a1.y), f2h2(a1.z,a1.w));
        As[0][r][(cbs + 1) ^ swz] = make_uint4(f2h2(a2.x,a2.y), f2h2(a2.z,a2.w),
                                               f2h2(a3.x,a3.y), f2h2(a3.z,a3.w));
        Bs[0][r][(cbs + 0) ^ swz] = make_uint4(f2h2(b0.x,b0.y), f2h2(b0.z,b0.w),
                                               f2h2(b1.x,b1.y), f2h2(b1.z,b1.w));
        Bs[0][r][(cbs + 1) ^ swz] = make_uint4(f2h2(b2.x,b2.y), f2h2(b2.z,b2.w),
                                               f2h2(b3.x,b3.y), f2h2(b3.z,b3.w));
    }
    __syncthreads();

    for (int it = 0; it < NIT; ++it) {
        const int buf = it & 1;
        const bool hasNext = (it + 1) < NIT;
        uint4 sa0, sa1, sb0, sb1;
        if (hasNext) {
            const float* An = Ag + (it + 1) * 32;
            const float* Bn = Bg + (it + 1) * 32;
            float4 a0 = *(const float4*)(An),     a1 = *(const float4*)(An + 4);
            float4 a2 = *(const float4*)(An + 8), a3 = *(const float4*)(An + 12);
            float4 b0 = *(const float4*)(Bn),     b1 = *(const float4*)(Bn + 4);
            float4 b2 = *(const float4*)(Bn + 8), b3 = *(const float4*)(Bn + 12);
            sa0 = make_uint4(f2h2(a0.x,a0.y), f2h2(a0.z,a0.w), f2h2(a1.x,a1.y), f2h2(a1.z,a1.w));
            sa1 = make_uint4(f2h2(a2.x,a2.y), f2h2(a2.z,a2.w), f2h2(a3.x,a3.y), f2h2(a3.z,a3.w));
            sb0 = make_uint4(f2h2(b0.x,b0.y), f2h2(b0.z,b0.w), f2h2(b1.x,b1.y), f2h2(b1.z,b1.w));
            sb1 = make_uint4(f2h2(b2.x,b2.y), f2h2(b2.z,b2.w), f2h2(b3.x,b3.y), f2h2(b3.z,b3.w));
        }

#pragma unroll
        for (int ks = 0; ks < 2; ++ks) {
            const int cbase = ks * 2;
            uint32_t af[2][4];
#pragma unroll
            for (int mi = 0; mi < 2; ++mi) {
                int ml = mBase + mi * 16 + (lane & 15);
                int ci = (cbase + (lane >> 4)) ^ ((ml >> 1) & 3);
                ldsm4(af[mi][0], af[mi][1], af[mi][2], af[mi][3],
                      smem_u32(&As[buf][ml][ci]));
            }
            uint32_t bf[4][4];
#pragma unroll
            for (int nj = 0; nj < 4; ++nj) {
                int nl = nBase + nj * 16 + ((lane >> 4) & 1) * 8 + (lane & 7);
                int ci = (cbase + ((lane >> 3) & 1)) ^ ((nl >> 1) & 3);
                ldsm4(bf[nj][0], bf[nj][1], bf[nj][2], bf[nj][3],
                      smem_u32(&Bs[buf][nl][ci]));
            }
#pragma unroll
            for (int mi = 0; mi < 2; ++mi)
#pragma unroll
                for (int nj = 0; nj < 4; ++nj) {
                    mma16816(acc[mi][nj * 2 + 0], af[mi], bf[nj][0], bf[nj][1]);
                    mma16816(acc[mi][nj * 2 + 1], af[mi], bf[nj][2], bf[nj][3]);
                }
        }

        if (hasNext) {
            const int nb = buf ^ 1;
            As[nb][r][(cbs + 0) ^ swz] = sa0;
            As[nb][r][(cbs + 1) ^ swz] = sa1;
            Bs[nb][r][(cbs + 0) ^ swz] = sb0;
            Bs[nb][r][(cbs + 1) ^ swz] = sb1;
            __syncthreads();
        }
    }

    // Epilogue: fragment rows g / g+8, cols 2*tig, 2*tig+1
#pragma unroll
    for (int mi = 0; mi < 2; ++mi) {
        int row0 = m0 + mBase + mi * 16 + g;
#pragma unroll
        for (int ni = 0; ni < 8; ++ni) {
            int col = n0 + nBase + ni * 8 + 2 * tig;
            float2 v0 = make_float2(acc[mi][ni][0], acc[mi][ni][1]);
            float2 v1 = make_float2(acc[mi][ni][2], acc[mi][ni][3]);
            if (FUSE) {
                float d0 = Dvec[col], d1 = Dvec[col + 1];
                float2 u0 = *(const float2*)(U + (size_t)row0 * HDIM + col);
                float2 u1 = *(const float2*)(U + (size_t)(row0 + 8) * HDIM + col);
                v0.x = fmaf(d0, u0.x, v0.x); v0.y = fmaf(d1, u0.y, v0.y);
                v1.x = fmaf(d0, u1.x, v1.x); v1.y = fmaf(d1, u1.y, v1.y);
            }
            *(float2*)(C + (size_t)row0 * NTOT + col) = v0;
            *(float2*)(C + (size_t)(row0 + 8) * NTOT + col) = v1;
        }
    }
}

// ---------------------------------------------------------------------------
// Scan phase A: per-(b,chunk,p) local recurrence -> carry (planar layout)
// ---------------------------------------------------------------------------
__global__ void s5_scan_local_kernel()
{
    int b = blockIdx.x / NCH;
    int c = blockIdx.x % NCH;
    int p = threadIdx.x;
    float lr = g_lam_re[p], li = g_lam_im[p];
    const float* base = g_S + (size_t)(b * LSEQ + c * CHUNK) * N1;
    float xr = 0.f, xi = 0.f;
#pragma unroll 8
    for (int t = 0; t < CHUNK; ++t) {
        float sr = base[t * N1 + p];
        float si = base[t * N1 + PDIM + p];
        float nr = fmaf(lr, xr, fmaf(-li, xi, sr));
        float ni = fmaf(lr, xi, fmaf(li, xr, si));
        xr = nr; xi = ni;
    }
    int idx = (b * NCH + c) * PDIM + p;
    g_car_re[idx] = xr;
    g_car_im[idx] = xi;
}

// Phase C: fold own exclusive prefix from carries (<=15 independent complex
// FMAs via the lamT-power table), apply recurrence, unscale on store.
__global__ void s5_scan_apply_kernel()
{
    int b = blockIdx.x / NCH;
    int c = blockIdx.x % NCH;
    int p = threadIdx.x;
    float lr = g_lam_re[p], li = g_lam_im[p];
    float inv = g_inv_scl[p];

    float xr = 0.f, xi = 0.f;
    for (int j = 0; j < c; ++j) {
        float pr = g_powT_re[c - 1 - j][p];
        float pi = g_powT_im[c - 1 - j][p];
        int idx = (b * NCH + j) * PDIM + p;
        float cr = g_car_re[idx], cim = g_car_im[idx];
        xr = fmaf(pr, cr, fmaf(-pi, cim, xr));
        xi = fmaf(pr, cim, fmaf(pi, cr, xi));
    }

    float* base = g_S + (size_t)(b * LSEQ + c * CHUNK) * N1;
#pragma unroll 4
    for (int t = 0; t < CHUNK; ++t) {
        float sr = base[t * N1 + p];
        float si = base[t * N1 + PDIM + p];
        float nr = fmaf(lr, xr, fmaf(-li, xi, sr));
        float ni = fmaf(lr, xi, fmaf(li, xr, si));
        xr = nr; xi = ni;
        base[t * N1 + p] = xr * inv;
        base[t * N1 + PDIM + p] = xi * inv;
    }
}

// ---------------------------------------------------------------------------
extern "C" void kernel_launch(void* const* d_in, const int* in_sizes, int n_in,
                              void* d_out, int out_size)
{
    const float* u   = (const float*)d_in[0];  // (16,1024,256)
    const float* Lre = (const float*)d_in[1];
    const float* Lim = (const float*)d_in[2];
    const float* Bp  = (const float*)d_in[3];  // (256,256,2)
    const float* Cp  = (const float*)d_in[4];  // (256,256,2)
    const float* Dv  = (const float*)d_in[5];  // (256,)
    const float* lst = (const float*)d_in[6];  // (256,1)
    float* out = (float*)d_out;                // (16,1024,256)

    float *sPtr, *wbPtr, *wcPtr;
    cudaGetSymbolAddress((void**)&sPtr,  g_S);
    cudaGetSymbolAddress((void**)&wbPtr, g_Wb);
    cudaGetSymbolAddress((void**)&wcPtr, g_Wc);

    // 1. discretize + repack weights + lamT power table + scaling
    s5_setup_kernel<<<PDIM, HDIM>>>(Lre, Lim, Bp, Cp, lst);

    // 2. Bu = u @ Wb^T   (fp16 tensor path, scaled)
    s5_mma_gemm<K1, N1, false><<<dim3(N1 / 128, MROWS / 128), 256>>>(
        u, wbPtr, sPtr, nullptr, nullptr);

    // 3. chunked complex scan over L (in place on g_S), 2 kernels
    s5_scan_local_kernel<<<BSZ * NCH, PDIM>>>();
    s5_scan_apply_kernel<<<BSZ * NCH, PDIM>>>();

    // 4. y = states @ Wc^T + D*u   (fp16 tensor path, fused epilogue)
    s5_mma_gemm<K3, N3, true><<<dim3(N3 / 128, MROWS / 128), 256>>>(
        sPtr, wcPtr, out, Dv, u);
}

// round 6
// speedup vs baseline: 2.6898x; 1.0803x over previous
#include <cuda_runtime.h>
#include <cuda_fp16.h>
#include <math.h>
#include <stdint.h>

// Problem dims
#define BSZ   16
#define LSEQ  1024
#define HDIM  256
#define PDIM  256
#define MROWS (BSZ*LSEQ)     // 16384
#define N1    (2*PDIM)       // 512  (interleaved re/im: col 2p, 2p+1)
#define K1    HDIM           // 256
#define N3    HDIM           // 256
#define K3    (2*PDIM)       // 512
#define CHUNK 128            // == GEMM1 M-tile
#define NCH   (LSEQ/CHUNK)   // 8

// Scratch (static device memory; no allocations allowed)
__device__ __align__(128) float  g_S[(size_t)MROWS * N1];    // 32 MB: y_local (scaled)
__device__ __align__(128) __half g_S16[(size_t)MROWS * N1];  // 16 MB: final states fp16
__device__ __align__(128) __half g_Wb16[N1 * K1];            // (512,256) N-major, K-contig
__device__ __align__(128) __half g_Wc16[N3 * K3];            // (256,512) N-major, K-contig
__device__ float g_lam_re[PDIM], g_lam_im[PDIM];             // Lambda_bar (scaled coef NOT applied)
__device__ float g_lam32_re[PDIM], g_lam32_im[PDIM];         // lam^32  (fp64-exact)
__device__ float g_powSeg_re[4][PDIM], g_powSeg_im[4][PDIM]; // lam^(32q+1)
__device__ float g_powT_re[NCH][PDIM], g_powT_im[NCH][PDIM]; // lam^(128j)
__device__ float g_inv_scl[PDIM];                            // 2^e unscale
__device__ __align__(128) float g_car[BSZ * NCH * PDIM * 2]; // per-chunk carries (float2)

// ---------------------------------------------------------------------------
// helpers
// ---------------------------------------------------------------------------
__device__ __forceinline__ uint32_t smem_u32(const void* p) {
    uint32_t a;
    asm("{ .reg .u64 t; cvta.to.shared.u64 t, %1; cvt.u32.u64 %0, t; }" : "=r"(a) : "l"(p));
    return a;
}
__device__ __forceinline__ uint32_t f2h2(float a, float b) {   // lo=a, hi=b
    uint32_t r;
    asm("cvt.rn.f16x2.f32 %0, %1, %2;" : "=r"(r) : "f"(b), "f"(a));
    return r;
}
__device__ __forceinline__ void ldsm4(uint32_t& r0, uint32_t& r1, uint32_t& r2,
                                      uint32_t& r3, uint32_t addr) {
    asm volatile("ldmatrix.sync.aligned.m8n8.x4.shared.b16 {%0,%1,%2,%3}, [%4];"
                 : "=r"(r0), "=r"(r1), "=r"(r2), "=r"(r3) : "r"(addr));
}
__device__ __forceinline__ void mma16816(float c[4], const uint32_t a[4],
                                         uint32_t b0, uint32_t b1) {
    asm volatile(
        "mma.sync.aligned.m16n8k16.row.col.f32.f16.f16.f32 "
        "{%0,%1,%2,%3}, {%4,%5,%6,%7}, {%8,%9}, {%0,%1,%2,%3};"
        : "+f"(c[0]), "+f"(c[1]), "+f"(c[2]), "+f"(c[3])
        : "r"(a[0]), "r"(a[1]), "r"(a[2]), "r"(a[3]), "r"(b0), "r"(b1));
}

// ---------------------------------------------------------------------------
// Setup: discretization, fp16 weight packing (interleaved re/im columns),
// fp64-exact power tables, per-p power-of-2 prescale of Wb.
// grid = PDIM, block = HDIM.
// ---------------------------------------------------------------------------
__global__ void s5_setup_kernel(const float* __restrict__ Lre,
                                const float* __restrict__ Lim,
                                const float* __restrict__ Bp,    // (P,H,2)
                                const float* __restrict__ Cp,    // (H,P,2)
                                const float* __restrict__ lstep) // (P,1)
{
    int p = blockIdx.x;
    int h = threadIdx.x;

    double lre = (double)Lre[p], lim = (double)Lim[p];
    double delta = exp((double)lstep[p]);
    double a = lre * delta, b = lim * delta;
    double ea = exp(a);
    double lam_r = ea * cos(b);
    double lam_i = ea * sin(b);
    double d2 = lre * lre + lim * lim;
    double nr = lam_r - 1.0, ni = lam_i;
    double cr = (nr * lre + ni * lim) / d2;
    double ci = (ni * lre - nr * lim) / d2;

    // power-of-2 prescale: |coef|*scl in [0.5, 1)
    int e;
    frexp(sqrt(cr * cr + ci * ci), &e);
    double scl = ldexp(1.0, -e);
    cr *= scl; ci *= scl;

    float br = Bp[((size_t)p * HDIM + h) * 2 + 0];
    float bi = Bp[((size_t)p * HDIM + h) * 2 + 1];
    g_Wb16[(size_t)(2 * p) * K1 + h]     = __float2half((float)(cr * br - ci * bi));
    g_Wb16[(size_t)(2 * p + 1) * K1 + h] = __float2half((float)(cr * bi + ci * br));

    float ccr = Cp[((size_t)h * PDIM + p) * 2 + 0];
    float cci = Cp[((size_t)h * PDIM + p) * 2 + 1];
    g_Wc16[(size_t)h * K3 + 2 * p]     = __float2half( 2.0f * ccr);
    g_Wc16[(size_t)h * K3 + 2 * p + 1] = __float2half(-2.0f * cci);

    if (h == 0) {
        g_lam_re[p] = (float)lam_r;
        g_lam_im[p] = (float)lam_i;
        g_inv_scl[p] = (float)ldexp(1.0, e);
        double a32 = a * 32.0, b32 = b * 32.0;
        double e32 = exp(a32);
        g_lam32_re[p] = (float)(e32 * cos(b32));
        g_lam32_im[p] = (float)(e32 * sin(b32));
    }
    if (h < 4) {   // lam^(32h+1)
        double aq = a * (32.0 * h + 1.0), bq = b * (32.0 * h + 1.0);
        double eq = exp(aq);
        g_powSeg_re[h][p] = (float)(eq * cos(bq));
        g_powSeg_im[h][p] = (float)(eq * sin(bq));
    }
    if (h < NCH) { // lam^(128h)
        double aT = a * (double)(CHUNK * h), bT = b * (double)(CHUNK * h);
        double eaT = exp(aT);
        g_powT_re[h][p] = (float)(eaT * cos(bT));
        g_powT_im[h][p] = (float)(eaT * sin(bT));
    }
}

// ---------------------------------------------------------------------------
// GEMM1 + fused chunk-local scan.
// C-tile 128x128 (M-tile == CHUNK), A = u fp32 (M,256), B = Wb16 (512,256).
// After MMA: stage tile in SMEM (overlapping k-loop buffers), scan 4 segments
// of 32 rows per complex column, combine with lam^32, emit chunk carry,
// write locally-scanned states (still scaled) to g_S.
// ---------------------------------------------------------------------------
#define G1_SMEM 70656   // max(32768 mainloop, 66560 Stile + 2*2048 carr/pref)

__global__ void __launch_bounds__(256)
s5_gemm1_scan(const float* __restrict__ U)
{
    extern __shared__ char sm[];
    uint4 (*As)[128][4] = (uint4 (*)[128][4])sm;            // [2][128][4]
    uint4 (*Bs)[128][4] = (uint4 (*)[128][4])(sm + 16384);
    float* Stile = (float*)sm;                              // 128 x 130 (post-loop)
    float* carrR = (float*)(sm + 66560);                    // [4][64]
    float* carrI = carrR + 256;
    float* prefR = carrI + 256;                             // [4][64]
    float* prefI = prefR + 256;

    const int t = threadIdx.x;
    const int lane = t & 31, w = t >> 5;
    const int g = lane >> 2, tig = lane & 3;
    const int mBase = (w & 3) * 32;
    const int nBase = (w >> 2) * 64;
    const int m0 = blockIdx.y * 128, n0 = blockIdx.x * 128;
    const int bIdx = m0 >> 10, cIdx = (m0 >> 7) & (NCH - 1);

    const int r  = t >> 1;
    const int kh = (t & 1) * 16;
    const int cbs = (t & 1) * 2;
    const int swz = (r >> 1) & 3;

    const float*  Ag = U + (size_t)(m0 + r) * K1 + kh;
    const __half* Bg = g_Wb16 + (size_t)(n0 + r) * K1 + kh;

    float acc[2][8][4];
#pragma unroll
    for (int mi = 0; mi < 2; ++mi)
#pragma unroll
        for (int ni = 0; ni < 8; ++ni)
#pragma unroll
            for (int q = 0; q < 4; ++q) acc[mi][ni][q] = 0.0f;

    // stage chunk 0
    {
        float4 a0 = *(const float4*)(Ag),     a1 = *(const float4*)(Ag + 4);
        float4 a2 = *(const float4*)(Ag + 8), a3 = *(const float4*)(Ag + 12);
        As[0][r][(cbs + 0) ^ swz] = make_uint4(f2h2(a0.x,a0.y), f2h2(a0.z,a0.w),
                                               f2h2(a1.x,a1.y), f2h2(a1.z,a1.w));
        As[0][r][(cbs + 1) ^ swz] = make_uint4(f2h2(a2.x,a2.y), f2h2(a2.z,a2.w),
                                               f2h2(a3.x,a3.y), f2h2(a3.z,a3.w));
        Bs[0][r][(cbs + 0) ^ swz] = *(const uint4*)(Bg);
        Bs[0][r][(cbs + 1) ^ swz] = *(const uint4*)(Bg + 8);
    }
    __syncthreads();

    const int NIT = K1 / 32;   // 8
    for (int it = 0; it < NIT; ++it) {
        const int buf = it & 1;
        const bool hasNext = (it + 1) < NIT;
        uint4 sa0, sa1, sb0, sb1;
        if (hasNext) {
            const float*  An = Ag + (it + 1) * 32;
            const __half* Bn = Bg + (it + 1) * 32;
            float4 a0 = *(const float4*)(An),     a1 = *(const float4*)(An + 4);
            float4 a2 = *(const float4*)(An + 8), a3 = *(const float4*)(An + 12);
            sa0 = make_uint4(f2h2(a0.x,a0.y), f2h2(a0.z,a0.w), f2h2(a1.x,a1.y), f2h2(a1.z,a1.w));
            sa1 = make_uint4(f2h2(a2.x,a2.y), f2h2(a2.z,a2.w), f2h2(a3.x,a3.y), f2h2(a3.z,a3.w));
            sb0 = *(const uint4*)(Bn);
            sb1 = *(const uint4*)(Bn + 8);
        }
#pragma unroll
        for (int ks = 0; ks < 2; ++ks) {
            const int cbase = ks * 2;
            uint32_t af[2][4];
#pragma unroll
            for (int mi = 0; mi < 2; ++mi) {
                int ml = mBase + mi * 16 + (lane & 15);
                int ci = (cbase + (lane >> 4)) ^ ((ml >> 1) & 3);
                ldsm4(af[mi][0], af[mi][1], af[mi][2], af[mi][3],
                      smem_u32(&As[buf][ml][ci]));
            }
            uint32_t bf[4][4];
#pragma unroll
            for (int nj = 0; nj < 4; ++nj) {
                int nl = nBase + nj * 16 + ((lane >> 4) & 1) * 8 + (lane & 7);
                int ci = (cbase + ((lane >> 3) & 1)) ^ ((nl >> 1) & 3);
                ldsm4(bf[nj][0], bf[nj][1], bf[nj][2], bf[nj][3],
                      smem_u32(&Bs[buf][nl][ci]));
            }
#pragma unroll
            for (int mi = 0; mi < 2; ++mi)
#pragma unroll
                for (int nj = 0; nj < 4; ++nj) {
                    mma16816(acc[mi][nj * 2 + 0], af[mi], bf[nj][0], bf[nj][1]);
                    mma16816(acc[mi][nj * 2 + 1], af[mi], bf[nj][2], bf[nj][3]);
                }
        }
        if (hasNext) {
            const int nb = buf ^ 1;
            As[nb][r][(cbs + 0) ^ swz] = sa0;
            As[nb][r][(cbs + 1) ^ swz] = sa1;
            Bs[nb][r][(cbs + 0) ^ swz] = sb0;
            Bs[nb][r][(cbs + 1) ^ swz] = sb1;
            __syncthreads();
        }
    }
    __syncthreads();   // mainloop smem dead; reuse as Stile

    // 1. accs -> Stile
#pragma unroll
    for (int mi = 0; mi < 2; ++mi) {
        int row = mBase + mi * 16 + g;
#pragma unroll
        for (int ni = 0; ni < 8; ++ni) {
            int col = nBase + ni * 8 + 2 * tig;
            *(float2*)(Stile + row * 130 + col) =
                make_float2(acc[mi][ni][0], acc[mi][ni][1]);
            *(float2*)(Stile + (row + 8) * 130 + col) =
                make_float2(acc[mi][ni][2], acc[mi][ni][3]);
        }
    }
    __syncthreads();

    // 2. segment-local scan (zero init), 4 segs x 64 complex cols
    const int pl = t & 63, seg = t >> 6;
    const int pg = (n0 >> 1) + pl;
    const float lr = g_lam_re[pg], li = g_lam_im[pg];
    {
        float yr = 0.f, yi = 0.f;
        float* colp = Stile + 2 * pl;
#pragma unroll 4
        for (int tt = 0; tt < 32; ++tt) {
            int row = seg * 32 + tt;
            float2 s = *(float2*)(colp + row * 130);
            float nyr = fmaf(lr, yr, fmaf(-li, yi, s.x));
            float nyi = fmaf(lr, yi, fmaf( li, yr, s.y));
            yr = nyr; yi = nyi;
            *(float2*)(colp + row * 130) = make_float2(yr, yi);
        }
        carrR[seg * 64 + pl] = yr;
        carrI[seg * 64 + pl] = yi;
    }
    __syncthreads();

    // 3. segment-carry combine (lam^32) + chunk carry out
    if (t < 64) {
        int pg2 = (n0 >> 1) + t;
        float l32r = g_lam32_re[pg2], l32i = g_lam32_im[pg2];
        float Pr = 0.f, Pi = 0.f;
#pragma unroll
        for (int q = 0; q < 4; ++q) {
            prefR[q * 64 + t] = Pr;
            prefI[q * 64 + t] = Pi;
            float cr = carrR[q * 64 + t], ci = carrI[q * 64 + t];
            float nPr = fmaf(l32r, Pr, fmaf(-l32i, Pi, cr));
            float nPi = fmaf(l32r, Pi, fmaf( l32i, Pr, ci));
            Pr = nPr; Pi = nPi;
        }
        *(float2*)(g_car + ((size_t)(bIdx * NCH + cIdx) * PDIM + pg2) * 2) =
            make_float2(Pr, Pi);
    }
    __syncthreads();

    // 4. apply seg prefix, write y_local to g_S
    {
        float Er = prefR[seg * 64 + pl], Ei = prefI[seg * 64 + pl];
        float wr = lr, wi = li;   // lam^1
        float* colp = Stile + 2 * pl;
#pragma unroll 4
        for (int tt = 0; tt < 32; ++tt) {
            int row = seg * 32 + tt;
            float2 s = *(float2*)(colp + row * 130);
            float xr = fmaf(wr, Er, fmaf(-wi, Ei, s.x));
            float xi = fmaf(wr, Ei, fmaf( wi, Er, s.y));
            *(float2*)(g_S + (size_t)(m0 + row) * N1 + n0 + 2 * pl) =
                make_float2(xr, xi);
            float nwr = fmaf(wr, lr, -wi * li);
            float nwi = fmaf(wr, li,  wi * lr);
            wr = nwr; wi = nwi;
        }
    }
}

// ---------------------------------------------------------------------------
// Phase C: elementwise prefix-apply + fp16 convert.
// grid = BSZ*NCH*4 (b, chunk, seg of 32 rows), block = 256 (p).
// x_t = y_t + lam^(t+1) * E;  E = sum_{j<c} lam^(128(c-1-j)) * carry_j.
// Writes final (unscaled) states as fp16 to g_S16.
// ---------------------------------------------------------------------------
__global__ void s5_scan_apply_kernel()
{
    int bx = blockIdx.x;
    int seg = bx & 3;
    int bc = bx >> 2;
    int c = bc & (NCH - 1);
    int b = bc >> 3;
    int p = threadIdx.x;

    float lr = g_lam_re[p], li = g_lam_im[p];
    float inv = g_inv_scl[p];

    float Er = 0.f, Ei = 0.f;
    for (int j = 0; j < c; ++j) {
        int d = c - 1 - j;
        float pr = g_powT_re[d][p], pi = g_powT_im[d][p];
        float2 cv = *(float2*)(g_car + ((size_t)(b * NCH + j) * PDIM + p) * 2);
        Er = fmaf(pr, cv.x, fmaf(-pi, cv.y, Er));
        Ei = fmaf(pr, cv.y, fmaf( pi, cv.x, Ei));
    }

    float wr = g_powSeg_re[seg][p], wi = g_powSeg_im[seg][p];  // lam^(32seg+1)
    size_t rowBase = (size_t)(b * LSEQ + c * CHUNK + seg * 32);
    const float* yp = g_S + rowBase * N1 + 2 * p;
    __half2* op = (__half2*)g_S16 + rowBase * PDIM + p;
#pragma unroll 4
    for (int tt = 0; tt < 32; ++tt) {
        float2 y = *(const float2*)(yp + (size_t)tt * N1);
        float xr = fmaf(wr, Er, fmaf(-wi, Ei, y.x));
        float xi = fmaf(wr, Ei, fmaf( wi, Er, y.y));
        op[(size_t)tt * PDIM] = __floats2half2_rn(xr * inv, xi * inv);
        float nwr = fmaf(wr, lr, -wi * li);
        float nwi = fmaf(wr, li,  wi * lr);
        wr = nwr; wi = nwi;
    }
}

// ---------------------------------------------------------------------------
// GEMM3: C = S16 @ Wc16^T + D*u.  Both operands fp16-direct, fused epilogue.
// ---------------------------------------------------------------------------
__global__ void __launch_bounds__(256, 2)
s5_gemm3(const __half* __restrict__ A,   // (M, 512) fp16
         const __half* __restrict__ B,   // (256, 512) fp16 N-major
         float* __restrict__ C,
         const float* __restrict__ Dvec,
         const float* __restrict__ U)
{
    __shared__ uint4 As[2][128][4];
    __shared__ uint4 Bs[2][128][4];

    const int t = threadIdx.x;
    const int lane = t & 31, w = t >> 5;
    const int g = lane >> 2, tig = lane & 3;
    const int mBase = (w & 3) * 32;
    const int nBase = (w >> 2) * 64;
    const int m0 = blockIdx.y * 128, n0 = blockIdx.x * 128;

    const int r  = t >> 1;
    const int kh = (t & 1) * 16;
    const int cbs = (t & 1) * 2;
    const int swz = (r >> 1) & 3;

    const __half* Ag = A + (size_t)(m0 + r) * K3 + kh;
    const __half* Bg = B + (size_t)(n0 + r) * K3 + kh;

    float acc[2][8][4];
#pragma unroll
    for (int mi = 0; mi < 2; ++mi)
#pragma unroll
        for (int ni = 0; ni < 8; ++ni)
#pragma unroll
            for (int q = 0; q < 4; ++q) acc[mi][ni][q] = 0.0f;

    As[0][r][(cbs + 0) ^ swz] = *(const uint4*)(Ag);
    As[0][r][(cbs + 1) ^ swz] = *(const uint4*)(Ag + 8);
    Bs[0][r][(cbs + 0) ^ swz] = *(const uint4*)(Bg);
    Bs[0][r][(cbs + 1) ^ swz] = *(const uint4*)(Bg + 8);
    __syncthreads();

    const int NIT = K3 / 32;   // 16
    for (int it = 0; it < NIT; ++it) {
        const int buf = it & 1;
        const bool hasNext = (it + 1) < NIT;
        uint4 sa0, sa1, sb0, sb1;
        if (hasNext) {
            const __half* An = Ag + (it + 1) * 32;
            const __half* Bn = Bg + (it + 1) * 32;
            sa0 = *(const uint4*)(An);
            sa1 = *(const uint4*)(An + 8);
            sb0 = *(const uint4*)(Bn);
            sb1 = *(const uint4*)(Bn + 8);
        }
#pragma unroll
        for (int ks = 0; ks < 2; ++ks) {
            const int cbase = ks * 2;
            uint32_t af[2][4];
#pragma unroll
            for (int mi = 0; mi < 2; ++mi) {
                int ml = mBase + mi * 16 + (lane & 15);
                int ci = (cbase + (lane >> 4)) ^ ((ml >> 1) & 3);
                ldsm4(af[mi][0], af[mi][1], af[mi][2], af[mi][3],
                      smem_u32(&As[buf][ml][ci]));
            }
            uint32_t bf[4][4];
#pragma unroll
            for (int nj = 0; nj < 4; ++nj) {
                int nl = nBase + nj * 16 + ((lane >> 4) & 1) * 8 + (lane & 7);
                int ci = (cbase + ((lane >> 3) & 1)) ^ ((nl >> 1) & 3);
                ldsm4(bf[nj][0], bf[nj][1], bf[nj][2], bf[nj][3],
                      smem_u32(&Bs[buf][nl][ci]));
            }
#pragma unroll
            for (int mi = 0; mi < 2; ++mi)
#pragma unroll
                for (int nj = 0; nj < 4; ++nj) {
                    mma16816(acc[mi][nj * 2 + 0], af[mi], bf[nj][0], bf[nj][1]);
                    mma16816(acc[mi][nj * 2 + 1], af[mi], bf[nj][2], bf[nj][3]);
                }
        }
        if (hasNext) {
            const int nb = buf ^ 1;
            As[nb][r][(cbs + 0) ^ swz] = sa0;
            As[nb][r][(cbs + 1) ^ swz] = sa1;
            Bs[nb][r][(cbs + 0) ^ swz] = sb0;
            Bs[nb][r][(cbs + 1) ^ swz] = sb1;
            __syncthreads();
        }
    }

    // Epilogue with D*u feedthrough
#pragma unroll
    for (int mi = 0; mi < 2; ++mi) {
        int row0 = m0 + mBase + mi * 16 + g;
#pragma unroll
        for (int ni = 0; ni < 8; ++ni) {
            int col = n0 + nBase + ni * 8 + 2 * tig;
            float d0 = Dvec[col], d1 = Dvec[col + 1];
            float2 u0 = *(const float2*)(U + (size_t)row0 * HDIM + col);
            float2 u1 = *(const float2*)(U + (size_t)(row0 + 8) * HDIM + col);
            float2 v0 = make_float2(fmaf(d0, u0.x, acc[mi][ni][0]),
                                    fmaf(d1, u0.y, acc[mi][ni][1]));
            float2 v1 = make_float2(fmaf(d0, u1.x, acc[mi][ni][2]),
                                    fmaf(d1, u1.y, acc[mi][ni][3]));
            *(float2*)(C + (size_t)row0 * N3 + col) = v0;
            *(float2*)(C + (size_t)(row0 + 8) * N3 + col) = v1;
        }
    }
}

// ---------------------------------------------------------------------------
extern "C" void kernel_launch(void* const* d_in, const int* in_sizes, int n_in,
                              void* d_out, int out_size)
{
    const float* u   = (const float*)d_in[0];  // (16,1024,256)
    const float* Lre = (const float*)d_in[1];
    const float* Lim = (const float*)d_in[2];
    const float* Bp  = (const float*)d_in[3];  // (256,256,2)
    const float* Cp  = (const float*)d_in[4];  // (256,256,2)
    const float* Dv  = (const float*)d_in[5];  // (256,)
    const float* lst = (const float*)d_in[6];  // (256,1)
    float* out = (float*)d_out;                // (16,1024,256)

    __half *s16Ptr, *wcPtr;
    cudaGetSymbolAddress((void**)&s16Ptr, g_S16);
    cudaGetSymbolAddress((void**)&wcPtr,  g_Wc16);

    cudaFuncSetAttribute(s5_gemm1_scan,
                         cudaFuncAttributeMaxDynamicSharedMemorySize, G1_SMEM);

    // 1. discretize + pack fp16 weights + power tables
    s5_setup_kernel<<<PDIM, HDIM>>>(Lre, Lim, Bp, Cp, lst);

    // 2. Bu GEMM + fused chunk-local scan -> y_local (g_S) + carries (g_car)
    s5_gemm1_scan<<<dim3(N1 / 128, MROWS / 128), 256, G1_SMEM>>>(u);

    // 3. prefix apply + fp16 convert -> final states (g_S16)
    s5_scan_apply_kernel<<<BSZ * NCH * 4, PDIM>>>();

    // 4. y = states16 @ Wc16^T + D*u
    s5_gemm3<<<dim3(N3 / 128, MROWS / 128), 256>>>(s16Ptr, wcPtr, out, Dv, u);
}

// round 7
// speedup vs baseline: 3.0328x; 1.1275x over previous
#include <cuda_runtime.h>
#include <cuda_fp16.h>
#include <math.h>
#include <stdint.h>

// Problem dims
#define BSZ   16
#define LSEQ  1024
#define HDIM  256
#define PDIM  256
#define MROWS (BSZ*LSEQ)     // 16384
#define N1    (2*PDIM)       // 512  (interleaved re/im: col 2p, 2p+1)
#define K1    HDIM           // 256
#define N3    HDIM           // 256
#define K3    (2*PDIM)       // 512
#define CHUNK 128            // == GEMM1 M-tile
#define NCH   (LSEQ/CHUNK)   // 8

// Scratch (static device memory; no allocations allowed)
__device__ __align__(128) float  g_S[(size_t)MROWS * N1];    // 32 MB: y_local (scaled)
__device__ __align__(128) __half g_S16[(size_t)MROWS * N1];  // 16 MB: final states fp16
__device__ __align__(128) __half g_u16[(size_t)MROWS * HDIM];// 8 MB: u in fp16
__device__ __align__(128) __half g_Wb16[N1 * K1];            // (512,256) N-major, K-contig
__device__ __align__(128) __half g_Wc16[N3 * K3];            // (256,512) N-major, K-contig
__device__ float g_lam_re[PDIM], g_lam_im[PDIM];
__device__ float g_lam32_re[PDIM], g_lam32_im[PDIM];         // lam^32  (fp64-exact)
__device__ float g_powSeg_re[4][PDIM], g_powSeg_im[4][PDIM]; // lam^(32q+1)
__device__ float g_powT_re[NCH][PDIM], g_powT_im[NCH][PDIM]; // lam^(128j)
__device__ float g_inv_scl[PDIM];
__device__ __align__(128) float g_car[BSZ * NCH * PDIM * 2];

// ---------------------------------------------------------------------------
// helpers
// ---------------------------------------------------------------------------
__device__ __forceinline__ uint32_t smem_u32(const void* p) {
    uint32_t a;
    asm("{ .reg .u64 t; cvta.to.shared.u64 t, %1; cvt.u32.u64 %0, t; }" : "=r"(a) : "l"(p));
    return a;
}
__device__ __forceinline__ uint32_t f2h2(float a, float b) {   // lo=a, hi=b
    uint32_t r;
    asm("cvt.rn.f16x2.f32 %0, %1, %2;" : "=r"(r) : "f"(b), "f"(a));
    return r;
}
__device__ __forceinline__ void cp_async16(uint32_t saddr, const void* gaddr) {
    asm volatile("cp.async.cg.shared.global [%0], [%1], 16;" :: "r"(saddr), "l"(gaddr));
}
#define CP_COMMIT() asm volatile("cp.async.commit_group;" ::: "memory")
#define CP_WAIT(n)  asm volatile("cp.async.wait_group %0;" :: "n"(n) : "memory")

__device__ __forceinline__ void ldsm4(uint32_t& r0, uint32_t& r1, uint32_t& r2,
                                      uint32_t& r3, uint32_t addr) {
    asm volatile("ldmatrix.sync.aligned.m8n8.x4.shared.b16 {%0,%1,%2,%3}, [%4];"
                 : "=r"(r0), "=r"(r1), "=r"(r2), "=r"(r3) : "r"(addr));
}
__device__ __forceinline__ void mma16816(float c[4], const uint32_t a[4],
                                         uint32_t b0, uint32_t b1) {
    asm volatile(
        "mma.sync.aligned.m16n8k16.row.col.f32.f16.f16.f32 "
        "{%0,%1,%2,%3}, {%4,%5,%6,%7}, {%8,%9}, {%0,%1,%2,%3};"
        : "+f"(c[0]), "+f"(c[1]), "+f"(c[2]), "+f"(c[3])
        : "r"(a[0]), "r"(a[1]), "r"(a[2]), "r"(a[3]), "r"(b0), "r"(b1));
}

// MMA block on one 32-k stage.  Fragment maps validated in round 5/6.
#define MMA_STAGE(stgAddr)                                                    \
    do {                                                                      \
        _Pragma("unroll")                                                     \
        for (int ks = 0; ks < 2; ++ks) {                                      \
            const int cbase = ks * 2;                                         \
            uint32_t af[2][4];                                                \
            _Pragma("unroll")                                                 \
            for (int mi = 0; mi < 2; ++mi) {                                  \
                int ml = mBase + mi * 16 + (lane & 15);                       \
                int ci = (cbase + (lane >> 4)) ^ ((ml >> 1) & 3);             \
                ldsm4(af[mi][0], af[mi][1], af[mi][2], af[mi][3],             \
                      (stgAddr) + ml * 64 + ci * 16);                         \
            }                                                                 \
            uint32_t bf[4][4];                                                \
            _Pragma("unroll")                                                 \
            for (int nj = 0; nj < 4; ++nj) {                                  \
                int nl = nBase + nj * 16 + ((lane >> 4) & 1) * 8 + (lane & 7);\
                int ci = (cbase + ((lane >> 3) & 1)) ^ ((nl >> 1) & 3);       \
                ldsm4(bf[nj][0], bf[nj][1], bf[nj][2], bf[nj][3],             \
                      (stgAddr) + 8192 + nl * 64 + ci * 16);                  \
            }                                                                 \
            _Pragma("unroll")                                                 \
            for (int mi = 0; mi < 2; ++mi)                                    \
                _Pragma("unroll")                                             \
                for (int nj = 0; nj < 4; ++nj) {                              \
                    mma16816(acc[mi][nj * 2 + 0], af[mi], bf[nj][0], bf[nj][1]);\
                    mma16816(acc[mi][nj * 2 + 1], af[mi], bf[nj][2], bf[nj][3]);\
                }                                                             \
        }                                                                     \
    } while (0)

// ---------------------------------------------------------------------------
// u -> fp16 conversion (one-shot).  grid = MROWS*HDIM/2048, block = 256.
// ---------------------------------------------------------------------------
__global__ void s5_u2h_kernel(const float* __restrict__ u)
{
    size_t i = ((size_t)blockIdx.x * 256 + threadIdx.x) * 8;
    float4 a = *(const float4*)(u + i);
    float4 b = *(const float4*)(u + i + 4);
    *(uint4*)(g_u16 + i) = make_uint4(f2h2(a.x, a.y), f2h2(a.z, a.w),
                                      f2h2(b.x, b.y), f2h2(b.z, b.w));
}

// ---------------------------------------------------------------------------
// Setup: discretization, fp16 weight packing (interleaved re/im columns),
// fp64-exact power tables, per-p power-of-2 prescale of Wb.
// ---------------------------------------------------------------------------
__global__ void s5_setup_kernel(const float* __restrict__ Lre,
                                const float* __restrict__ Lim,
                                const float* __restrict__ Bp,
                                const float* __restrict__ Cp,
                                const float* __restrict__ lstep)
{
    int p = blockIdx.x;
    int h = threadIdx.x;

    double lre = (double)Lre[p], lim = (double)Lim[p];
    double delta = exp((double)lstep[p]);
    double a = lre * delta, b = lim * delta;
    double ea = exp(a);
    double lam_r = ea * cos(b);
    double lam_i = ea * sin(b);
    double d2 = lre * lre + lim * lim;
    double nr = lam_r - 1.0, ni = lam_i;
    double cr = (nr * lre + ni * lim) / d2;
    double ci = (ni * lre - nr * lim) / d2;

    int e;
    frexp(sqrt(cr * cr + ci * ci), &e);
    double scl = ldexp(1.0, -e);
    cr *= scl; ci *= scl;

    float br = Bp[((size_t)p * HDIM + h) * 2 + 0];
    float bi = Bp[((size_t)p * HDIM + h) * 2 + 1];
    g_Wb16[(size_t)(2 * p) * K1 + h]     = __float2half((float)(cr * br - ci * bi));
    g_Wb16[(size_t)(2 * p + 1) * K1 + h] = __float2half((float)(cr * bi + ci * br));

    float ccr = Cp[((size_t)h * PDIM + p) * 2 + 0];
    float cci = Cp[((size_t)h * PDIM + p) * 2 + 1];
    g_Wc16[(size_t)h * K3 + 2 * p]     = __float2half( 2.0f * ccr);
    g_Wc16[(size_t)h * K3 + 2 * p + 1] = __float2half(-2.0f * cci);

    if (h == 0) {
        g_lam_re[p] = (float)lam_r;
        g_lam_im[p] = (float)lam_i;
        g_inv_scl[p] = (float)ldexp(1.0, e);
        double a32 = a * 32.0, b32 = b * 32.0;
        double e32 = exp(a32);
        g_lam32_re[p] = (float)(e32 * cos(b32));
        g_lam32_im[p] = (float)(e32 * sin(b32));
    }
    if (h < 4) {
        double aq = a * (32.0 * h + 1.0), bq = b * (32.0 * h + 1.0);
        double eq = exp(aq);
        g_powSeg_re[h][p] = (float)(eq * cos(bq));
        g_powSeg_im[h][p] = (float)(eq * sin(bq));
    }
    if (h < NCH) {
        double aT = a * (double)(CHUNK * h), bT = b * (double)(CHUNK * h);
        double eaT = exp(aT);
        g_powT_re[h][p] = (float)(eaT * cos(bT));
        g_powT_im[h][p] = (float)(eaT * sin(bT));
    }
}

// ---------------------------------------------------------------------------
// GEMM1 + fused chunk-local scan.  cp.async 4-stage pipeline.
// Stage layout: [slot 16KB] = A 128x32h (8KB, 64B rows, xor-swizzled 16B
// chunks) + B same at +8192.
// ---------------------------------------------------------------------------
#define G1_SMEM 70656   // max(65536 pipeline, 66560 Stile + 4096 carries)

__global__ void __launch_bounds__(256)
s5_gemm1_scan(const float* __restrict__ Ufp32)
{
    extern __shared__ char sm[];
    uint32_t sb = smem_u32(sm);

    const int t = threadIdx.x;
    const int lane = t & 31, w = t >> 5;
    const int g = lane >> 2, tig = lane & 3;
    const int mBase = (w & 3) * 32;
    const int nBase = (w >> 2) * 64;
    const int m0 = blockIdx.y * 128, n0 = blockIdx.x * 128;
    const int bIdx = m0 >> 10, cIdx = (m0 >> 7) & (NCH - 1);

    const int r0 = t >> 2, c0 = t & 3;
    const uint32_t sAoff = r0 * 64 + (((uint32_t)(c0 ^ ((r0 >> 1) & 3))) << 4);
    const __half* Ag = g_u16 + (size_t)(m0 + r0) * K1 + c0 * 8;
    const __half* Bg = g_Wb16 + (size_t)(n0 + r0) * K1 + c0 * 8;

    auto issue = [&](int slot, int kof) {
        uint32_t base = sb + slot * 16384;
        cp_async16(base + sAoff,        Ag + kof);
        cp_async16(base + sAoff + 4096, Ag + kof + (size_t)64 * K1);
        cp_async16(base + sAoff + 8192, Bg + kof);
        cp_async16(base + sAoff + 12288,Bg + kof + (size_t)64 * K1);
    };

    float acc[2][8][4];
#pragma unroll
    for (int mi = 0; mi < 2; ++mi)
#pragma unroll
        for (int ni = 0; ni < 8; ++ni)
#pragma unroll
            for (int q = 0; q < 4; ++q) acc[mi][ni][q] = 0.0f;

    issue(0, 0);  CP_COMMIT();
    issue(1, 32); CP_COMMIT();
    issue(2, 64); CP_COMMIT();

    const int NIT = K1 / 32;   // 8
    for (int it = 0; it < NIT; ++it) {
        CP_WAIT(2);
        __syncthreads();
        uint32_t stg = sb + (it & 3) * 16384;
        MMA_STAGE(stg);
        if (it + 3 < NIT) issue((it + 3) & 3, (it + 3) * 32);
        CP_COMMIT();
    }
    CP_WAIT(0);
    __syncthreads();   // pipeline smem dead; reuse as Stile

    float* Stile = (float*)sm;              // 128 x 130
    float* carrR = (float*)(sm + 66560);    // [4][64]
    float* carrI = carrR + 256;
    float* prefR = carrI + 256;
    float* prefI = prefR + 256;

    // 1. accs -> Stile
#pragma unroll
    for (int mi = 0; mi < 2; ++mi) {
        int row = mBase + mi * 16 + g;
#pragma unroll
        for (int ni = 0; ni < 8; ++ni) {
            int col = nBase + ni * 8 + 2 * tig;
            *(float2*)(Stile + row * 130 + col) =
                make_float2(acc[mi][ni][0], acc[mi][ni][1]);
            *(float2*)(Stile + (row + 8) * 130 + col) =
                make_float2(acc[mi][ni][2], acc[mi][ni][3]);
        }
    }
    __syncthreads();

    // 2. segment-local scan (zero init), 4 segs x 64 complex cols
    const int pl = t & 63, seg = t >> 6;
    const int pg = (n0 >> 1) + pl;
    const float lr = g_lam_re[pg], li = g_lam_im[pg];
    {
        float yr = 0.f, yi = 0.f;
        float* colp = Stile + 2 * pl;
#pragma unroll 4
        for (int tt = 0; tt < 32; ++tt) {
            int row = seg * 32 + tt;
            float2 s = *(float2*)(colp + row * 130);
            float nyr = fmaf(lr, yr, fmaf(-li, yi, s.x));
            float nyi = fmaf(lr, yi, fmaf( li, yr, s.y));
            yr = nyr; yi = nyi;
            *(float2*)(colp + row * 130) = make_float2(yr, yi);
        }
        carrR[seg * 64 + pl] = yr;
        carrI[seg * 64 + pl] = yi;
    }
    __syncthreads();

    // 3. segment-carry combine (lam^32) + chunk carry out
    if (t < 64) {
        int pg2 = (n0 >> 1) + t;
        float l32r = g_lam32_re[pg2], l32i = g_lam32_im[pg2];
        float Pr = 0.f, Pi = 0.f;
#pragma unroll
        for (int q = 0; q < 4; ++q) {
            prefR[q * 64 + t] = Pr;
            prefI[q * 64 + t] = Pi;
            float cr = carrR[q * 64 + t], ci = carrI[q * 64 + t];
            float nPr = fmaf(l32r, Pr, fmaf(-l32i, Pi, cr));
            float nPi = fmaf(l32r, Pi, fmaf( l32i, Pr, ci));
            Pr = nPr; Pi = nPi;
        }
        *(float2*)(g_car + ((size_t)(bIdx * NCH + cIdx) * PDIM + pg2) * 2) =
            make_float2(Pr, Pi);
    }
    __syncthreads();

    // 4. apply seg prefix, write y_local to g_S
    {
        float Er = prefR[seg * 64 + pl], Ei = prefI[seg * 64 + pl];
        float wr = lr, wi = li;
        float* colp = Stile + 2 * pl;
#pragma unroll 4
        for (int tt = 0; tt < 32; ++tt) {
            int row = seg * 32 + tt;
            float2 s = *(float2*)(colp + row * 130);
            float xr = fmaf(wr, Er, fmaf(-wi, Ei, s.x));
            float xi = fmaf(wr, Ei, fmaf( wi, Er, s.y));
            *(float2*)(g_S + (size_t)(m0 + row) * N1 + n0 + 2 * pl) =
                make_float2(xr, xi);
            float nwr = fmaf(wr, lr, -wi * li);
            float nwi = fmaf(wr, li,  wi * lr);
            wr = nwr; wi = nwi;
        }
    }
}

// ---------------------------------------------------------------------------
// Phase C: elementwise prefix-apply + fp16 convert (unchanged).
// ---------------------------------------------------------------------------
__global__ void s5_scan_apply_kernel()
{
    int bx = blockIdx.x;
    int seg = bx & 3;
    int bc = bx >> 2;
    int c = bc & (NCH - 1);
    int b = bc >> 3;
    int p = threadIdx.x;

    float lr = g_lam_re[p], li = g_lam_im[p];
    float inv = g_inv_scl[p];

    float Er = 0.f, Ei = 0.f;
    for (int j = 0; j < c; ++j) {
        int d = c - 1 - j;
        float pr = g_powT_re[d][p], pi = g_powT_im[d][p];
        float2 cv = *(float2*)(g_car + ((size_t)(b * NCH + j) * PDIM + p) * 2);
        Er = fmaf(pr, cv.x, fmaf(-pi, cv.y, Er));
        Ei = fmaf(pr, cv.y, fmaf( pi, cv.x, Ei));
    }

    float wr = g_powSeg_re[seg][p], wi = g_powSeg_im[seg][p];
    size_t rowBase = (size_t)(b * LSEQ + c * CHUNK + seg * 32);
    const float* yp = g_S + rowBase * N1 + 2 * p;
    __half2* op = (__half2*)g_S16 + rowBase * PDIM + p;
#pragma unroll 4
    for (int tt = 0; tt < 32; ++tt) {
        float2 y = *(const float2*)(yp + (size_t)tt * N1);
        float xr = fmaf(wr, Er, fmaf(-wi, Ei, y.x));
        float xi = fmaf(wr, Ei, fmaf( wi, Er, y.y));
        op[(size_t)tt * PDIM] = __floats2half2_rn(xr * inv, xi * inv);
        float nwr = fmaf(wr, lr, -wi * li);
        float nwi = fmaf(wr, li,  wi * lr);
        wr = nwr; wi = nwi;
    }
}

// ---------------------------------------------------------------------------
// GEMM3: C = S16 @ Wc16^T + D*u.  cp.async 4-stage pipeline, fused epilogue.
// ---------------------------------------------------------------------------
#define G3_SMEM 65536

__global__ void __launch_bounds__(256)
s5_gemm3(float* __restrict__ C,
         const float* __restrict__ Dvec,
         const float* __restrict__ U)
{
    extern __shared__ char sm[];
    uint32_t sb = smem_u32(sm);

    const int t = threadIdx.x;
    const int lane = t & 31, w = t >> 5;
    const int g = lane >> 2, tig = lane & 3;
    const int mBase = (w & 3) * 32;
    const int nBase = (w >> 2) * 64;
    const int m0 = blockIdx.y * 128, n0 = blockIdx.x * 128;

    const int r0 = t >> 2, c0 = t & 3;
    const uint32_t sAoff = r0 * 64 + (((uint32_t)(c0 ^ ((r0 >> 1) & 3))) << 4);
    const __half* Ag = g_S16 + (size_t)(m0 + r0) * K3 + c0 * 8;
    const __half* Bg = g_Wc16 + (size_t)(n0 + r0) * K3 + c0 * 8;

    auto issue = [&](int slot, int kof) {
        uint32_t base = sb + slot * 16384;
        cp_async16(base + sAoff,        Ag + kof);
        cp_async16(base + sAoff + 4096, Ag + kof + (size_t)64 * K3);
        cp_async16(base + sAoff + 8192, Bg + kof);
        cp_async16(base + sAoff + 12288,Bg + kof + (size_t)64 * K3);
    };

    float acc[2][8][4];
#pragma unroll
    for (int mi = 0; mi < 2; ++mi)
#pragma unroll
        for (int ni = 0; ni < 8; ++ni)
#pragma unroll
            for (int q = 0; q < 4; ++q) acc[mi][ni][q] = 0.0f;

    issue(0, 0);  CP_COMMIT();
    issue(1, 32); CP_COMMIT();
    issue(2, 64); CP_COMMIT();

    const int NIT = K3 / 32;   // 16
    for (int it = 0; it < NIT; ++it) {
        CP_WAIT(2);
        __syncthreads();
        uint32_t stg = sb + (it & 3) * 16384;
        MMA_STAGE(stg);
        if (it + 3 < NIT) issue((it + 3) & 3, (it + 3) * 32);
        CP_COMMIT();
    }

    // Epilogue with D*u feedthrough
#pragma unroll
    for (int mi = 0; mi < 2; ++mi) {
        int row0 = m0 + mBase + mi * 16 + g;
#pragma unroll
        for (int ni = 0; ni < 8; ++ni) {
            int col = n0 + nBase + ni * 8 + 2 * tig;
            float d0 = Dvec[col], d1 = Dvec[col + 1];
            float2 u0 = *(const float2*)(U + (size_t)row0 * HDIM + col);
            float2 u1 = *(const float2*)(U + (size_t)(row0 + 8) * HDIM + col);
            float2 v0 = make_float2(fmaf(d0, u0.x, acc[mi][ni][0]),
                                    fmaf(d1, u0.y, acc[mi][ni][1]));
            float2 v1 = make_float2(fmaf(d0, u1.x, acc[mi][ni][2]),
                                    fmaf(d1, u1.y, acc[mi][ni][3]));
            *(float2*)(C + (size_t)row0 * N3 + col) = v0;
            *(float2*)(C + (size_t)(row0 + 8) * N3 + col) = v1;
        }
    }
}

// ---------------------------------------------------------------------------
extern "C" void kernel_launch(void* const* d_in, const int* in_sizes, int n_in,
                              void* d_out, int out_size)
{
    const float* u   = (const float*)d_in[0];
    const float* Lre = (const float*)d_in[1];
    const float* Lim = (const float*)d_in[2];
    const float* Bp  = (const float*)d_in[3];
    const float* Cp  = (const float*)d_in[4];
    const float* Dv  = (const float*)d_in[5];
    const float* lst = (const float*)d_in[6];
    float* out = (float*)d_out;

    cudaFuncSetAttribute(s5_gemm1_scan,
                         cudaFuncAttributeMaxDynamicSharedMemorySize, G1_SMEM);
    cudaFuncSetAttribute(s5_gemm3,
                         cudaFuncAttributeMaxDynamicSharedMemorySize, G3_SMEM);

    // 1. discretize + pack fp16 weights + power tables;  u -> fp16
    s5_setup_kernel<<<PDIM, HDIM>>>(Lre, Lim, Bp, Cp, lst);
    s5_u2h_kernel<<<(MROWS * HDIM) / 2048, 256>>>(u);

    // 2. Bu GEMM + fused chunk-local scan -> y_local (g_S) + carries (g_car)
    s5_gemm1_scan<<<dim3(N1 / 128, MROWS / 128), 256, G1_SMEM>>>(u);

    // 3. prefix apply + fp16 convert -> final states (g_S16)
    s5_scan_apply_kernel<<<BSZ * NCH * 4, PDIM>>>();

    // 4. y = states16 @ Wc16^T + D*u
    s5_gemm3<<<dim3(N3 / 128, MROWS / 128), 256, G3_SMEM>>>(out, Dv, u);
}

// round 8
// speedup vs baseline: 3.3844x; 1.1160x over previous
#include <cuda_runtime.h>
#include <cuda_fp16.h>
#include <math.h>
#include <stdint.h>

// Problem dims
#define BSZ   16
#define LSEQ  1024
#define HDIM  256
#define PDIM  256
#define MROWS (BSZ*LSEQ)     // 16384
#define N1    (2*PDIM)       // 512  (interleaved re/im: col 2p, 2p+1)
#define K1    HDIM           // 256
#define N3    HDIM           // 256
#define K3    (2*PDIM)       // 512
#define CHUNK 128            // == GEMM1 M-tile
#define NCH   (LSEQ/CHUNK)   // 8

// Scratch (static device memory; no allocations allowed)
__device__ __align__(128) __half g_S16[(size_t)MROWS * N1];  // 16 MB: final states fp16
__device__ __align__(128) __half g_u16[(size_t)MROWS * HDIM];// 8 MB: u in fp16
__device__ __align__(128) __half g_Wb16[N1 * K1];            // (512,256) N-major, K-contig
__device__ __align__(128) __half g_Wc16[N3 * K3];            // (256,512) N-major, K-contig
__device__ float g_lam_re[PDIM], g_lam_im[PDIM];
__device__ float g_lam32_re[PDIM], g_lam32_im[PDIM];         // lam^32   (fp64-exact)
__device__ float g_pow32_re[4][PDIM], g_pow32_im[4][PDIM];   // lam^(32q)
__device__ float g_powT_re[NCH][PDIM], g_powT_im[NCH][PDIM]; // lam^(128j)
__device__ float g_inv_scl[PDIM];
__device__ __align__(128) float    g_car[BSZ * NCH * PDIM * 2]; // chunk aggregates
__device__ __align__(128) unsigned g_flag[BSZ * NCH * PDIM];    // per-p publish flags

// ---------------------------------------------------------------------------
// helpers
// ---------------------------------------------------------------------------
__device__ __forceinline__ uint32_t smem_u32(const void* p) {
    uint32_t a;
    asm("{ .reg .u64 t; cvta.to.shared.u64 t, %1; cvt.u32.u64 %0, t; }" : "=r"(a) : "l"(p));
    return a;
}
__device__ __forceinline__ uint32_t f2h2(float a, float b) {   // lo=a, hi=b
    uint32_t r;
    asm("cvt.rn.f16x2.f32 %0, %1, %2;" : "=r"(r) : "f"(b), "f"(a));
    return r;
}
__device__ __forceinline__ void cp_async16(uint32_t saddr, const void* gaddr) {
    asm volatile("cp.async.cg.shared.global [%0], [%1], 16;" :: "r"(saddr), "l"(gaddr));
}
#define CP_COMMIT() asm volatile("cp.async.commit_group;" ::: "memory")
#define CP_WAIT(n)  asm volatile("cp.async.wait_group %0;" :: "n"(n) : "memory")

__device__ __forceinline__ void st_release_u32(unsigned* p, unsigned v) {
    asm volatile("st.release.gpu.global.u32 [%0], %1;" :: "l"(p), "r"(v) : "memory");
}
__device__ __forceinline__ unsigned ld_acquire_u32(const unsigned* p) {
    unsigned v;
    asm volatile("ld.acquire.gpu.global.u32 %0, [%1];" : "=r"(v) : "l"(p) : "memory");
    return v;
}
__device__ __forceinline__ float2 ld_relaxed_f2(const float* p) {
    float2 v;
    asm volatile("ld.relaxed.gpu.global.v2.f32 {%0,%1}, [%2];"
                 : "=f"(v.x), "=f"(v.y) : "l"(p) : "memory");
    return v;
}

__device__ __forceinline__ void ldsm4(uint32_t& r0, uint32_t& r1, uint32_t& r2,
                                      uint32_t& r3, uint32_t addr) {
    asm volatile("ldmatrix.sync.aligned.m8n8.x4.shared.b16 {%0,%1,%2,%3}, [%4];"
                 : "=r"(r0), "=r"(r1), "=r"(r2), "=r"(r3) : "r"(addr));
}
__device__ __forceinline__ void mma16816(float c[4], const uint32_t a[4],
                                         uint32_t b0, uint32_t b1) {
    asm volatile(
        "mma.sync.aligned.m16n8k16.row.col.f32.f16.f16.f32 "
        "{%0,%1,%2,%3}, {%4,%5,%6,%7}, {%8,%9}, {%0,%1,%2,%3};"
        : "+f"(c[0]), "+f"(c[1]), "+f"(c[2]), "+f"(c[3])
        : "r"(a[0]), "r"(a[1]), "r"(a[2]), "r"(a[3]), "r"(b0), "r"(b1));
}

// MMA block on one 32-k stage (fragment maps validated rounds 5-7).
#define MMA_STAGE(stgAddr)                                                    \
    do {                                                                      \
        _Pragma("unroll")                                                     \
        for (int ks = 0; ks < 2; ++ks) {                                      \
            const int cbase = ks * 2;                                         \
            uint32_t af[2][4];                                                \
            _Pragma("unroll")                                                 \
            for (int mi = 0; mi < 2; ++mi) {                                  \
                int ml = mBase + mi * 16 + (lane & 15);                       \
                int ci = (cbase + (lane >> 4)) ^ ((ml >> 1) & 3);             \
                ldsm4(af[mi][0], af[mi][1], af[mi][2], af[mi][3],             \
                      (stgAddr) + ml * 64 + ci * 16);                         \
            }                                                                 \
            uint32_t bf[4][4];                                                \
            _Pragma("unroll")                                                 \
            for (int nj = 0; nj < 4; ++nj) {                                  \
                int nl = nBase + nj * 16 + ((lane >> 4) & 1) * 8 + (lane & 7);\
                int ci = (cbase + ((lane >> 3) & 1)) ^ ((nl >> 1) & 3);       \
                ldsm4(bf[nj][0], bf[nj][1], bf[nj][2], bf[nj][3],             \
                      (stgAddr) + 8192 + nl * 64 + ci * 16);                  \
            }                                                                 \
            _Pragma("unroll")                                                 \
            for (int mi = 0; mi < 2; ++mi)                                    \
                _Pragma("unroll")                                             \
                for (int nj = 0; nj < 4; ++nj) {                              \
                    mma16816(acc[mi][nj * 2 + 0], af[mi], bf[nj][0], bf[nj][1]);\
                    mma16816(acc[mi][nj * 2 + 1], af[mi], bf[nj][2], bf[nj][3]);\
                }                                                             \
        }                                                                     \
    } while (0)

// ---------------------------------------------------------------------------
// u -> fp16 conversion + flag clear (one-shot).  grid = 2048, block = 256.
// ---------------------------------------------------------------------------
__global__ void s5_u2h_kernel(const float* __restrict__ u)
{
    size_t i = ((size_t)blockIdx.x * 256 + threadIdx.x) * 8;
    float4 a = *(const float4*)(u + i);
    float4 b = *(const float4*)(u + i + 4);
    *(uint4*)(g_u16 + i) = make_uint4(f2h2(a.x, a.y), f2h2(a.z, a.w),
                                      f2h2(b.x, b.y), f2h2(b.z, b.w));
    if (blockIdx.x < 32) {   // clear 32768 flags (8192 uint4)
        ((uint4*)g_flag)[blockIdx.x * 256 + threadIdx.x] =
            make_uint4(0u, 0u, 0u, 0u);
    }
}

// ---------------------------------------------------------------------------
// Setup: discretization, fp16 weight packing, fp64-exact power tables,
// per-p power-of-2 prescale of Wb.  grid = PDIM, block = HDIM.
// ---------------------------------------------------------------------------
__global__ void s5_setup_kernel(const float* __restrict__ Lre,
                                const float* __restrict__ Lim,
                                const float* __restrict__ Bp,
                                const float* __restrict__ Cp,
                                const float* __restrict__ lstep)
{
    int p = blockIdx.x;
    int h = threadIdx.x;

    double lre = (double)Lre[p], lim = (double)Lim[p];
    double delta = exp((double)lstep[p]);
    double a = lre * delta, b = lim * delta;
    double ea = exp(a);
    double lam_r = ea * cos(b);
    double lam_i = ea * sin(b);
    double d2 = lre * lre + lim * lim;
    double nr = lam_r - 1.0, ni = lam_i;
    double cr = (nr * lre + ni * lim) / d2;
    double ci = (ni * lre - nr * lim) / d2;

    int e;
    frexp(sqrt(cr * cr + ci * ci), &e);
    double scl = ldexp(1.0, -e);
    cr *= scl; ci *= scl;

    float br = Bp[((size_t)p * HDIM + h) * 2 + 0];
    float bi = Bp[((size_t)p * HDIM + h) * 2 + 1];
    g_Wb16[(size_t)(2 * p) * K1 + h]     = __float2half((float)(cr * br - ci * bi));
    g_Wb16[(size_t)(2 * p + 1) * K1 + h] = __float2half((float)(cr * bi + ci * br));

    float ccr = Cp[((size_t)h * PDIM + p) * 2 + 0];
    float cci = Cp[((size_t)h * PDIM + p) * 2 + 1];
    g_Wc16[(size_t)h * K3 + 2 * p]     = __float2half( 2.0f * ccr);
    g_Wc16[(size_t)h * K3 + 2 * p + 1] = __float2half(-2.0f * cci);

    if (h == 0) {
        g_lam_re[p] = (float)lam_r;
        g_lam_im[p] = (float)lam_i;
        g_inv_scl[p] = (float)ldexp(1.0, e);
        double a32 = a * 32.0, b32 = b * 32.0;
        double e32 = exp(a32);
        g_lam32_re[p] = (float)(e32 * cos(b32));
        g_lam32_im[p] = (float)(e32 * sin(b32));
    }
    if (h < 4) {   // lam^(32h)
        double aq = a * 32.0 * h, bq = b * 32.0 * h;
        double eq = exp(aq);
        g_pow32_re[h][p] = (float)(eq * cos(bq));
        g_pow32_im[h][p] = (float)(eq * sin(bq));
    }
    if (h < NCH) { // lam^(128h)
        double aT = a * (double)(CHUNK * h), bT = b * (double)(CHUNK * h);
        double eaT = exp(aT);
        g_powT_re[h][p] = (float)(eaT * cos(bT));
        g_powT_im[h][p] = (float)(eaT * sin(bT));
    }
}

// ---------------------------------------------------------------------------
// GEMM1 + fused FULL scan (chunk-local + decoupled-lookback cross-chunk).
// Writes final states fp16 directly to g_S16.  cp.async 4-stage pipeline.
// ---------------------------------------------------------------------------
#define G1_SMEM 70656   // max(65536 pipeline, 66560 Stile + 4096 carries)

__global__ void __launch_bounds__(256)
s5_gemm1_scan()
{
    extern __shared__ char sm[];
    uint32_t sb = smem_u32(sm);

    const int t = threadIdx.x;
    const int lane = t & 31, w = t >> 5;
    const int g = lane >> 2, tig = lane & 3;
    const int mBase = (w & 3) * 32;
    const int nBase = (w >> 2) * 64;
    const int m0 = blockIdx.y * 128, n0 = blockIdx.x * 128;
    const int bIdx = m0 >> 10, cIdx = (m0 >> 7) & (NCH - 1);

    const int r0 = t >> 2, c0 = t & 3;
    const uint32_t sAoff = r0 * 64 + (((uint32_t)(c0 ^ ((r0 >> 1) & 3))) << 4);
    const __half* Ag = g_u16 + (size_t)(m0 + r0) * K1 + c0 * 8;
    const __half* Bg = g_Wb16 + (size_t)(n0 + r0) * K1 + c0 * 8;

    auto issue = [&](int slot, int kof) {
        uint32_t base = sb + slot * 16384;
        cp_async16(base + sAoff,        Ag + kof);
        cp_async16(base + sAoff + 4096, Ag + kof + (size_t)64 * K1);
        cp_async16(base + sAoff + 8192, Bg + kof);
        cp_async16(base + sAoff + 12288,Bg + kof + (size_t)64 * K1);
    };

    float acc[2][8][4];
#pragma unroll
    for (int mi = 0; mi < 2; ++mi)
#pragma unroll
        for (int ni = 0; ni < 8; ++ni)
#pragma unroll
            for (int q = 0; q < 4; ++q) acc[mi][ni][q] = 0.0f;

    issue(0, 0);  CP_COMMIT();
    issue(1, 32); CP_COMMIT();
    issue(2, 64); CP_COMMIT();

    const int NIT = K1 / 32;   // 8
    for (int it = 0; it < NIT; ++it) {
        CP_WAIT(2);
        __syncthreads();
        uint32_t stg = sb + (it & 3) * 16384;
        MMA_STAGE(stg);
        if (it + 3 < NIT) issue((it + 3) & 3, (it + 3) * 32);
        CP_COMMIT();
    }
    CP_WAIT(0);
    __syncthreads();   // pipeline smem dead; reuse as Stile

    float* Stile = (float*)sm;              // 128 x 130
    float* carrR = (float*)(sm + 66560);    // [4][64]  (later: E_chunk [64])
    float* carrI = carrR + 256;
    float* prefR = carrI + 256;             // [4][64]
    float* prefI = prefR + 256;

    // 1. accs -> Stile
#pragma unroll
    for (int mi = 0; mi < 2; ++mi) {
        int row = mBase + mi * 16 + g;
#pragma unroll
        for (int ni = 0; ni < 8; ++ni) {
            int col = nBase + ni * 8 + 2 * tig;
            *(float2*)(Stile + row * 130 + col) =
                make_float2(acc[mi][ni][0], acc[mi][ni][1]);
            *(float2*)(Stile + (row + 8) * 130 + col) =
                make_float2(acc[mi][ni][2], acc[mi][ni][3]);
        }
    }
    __syncthreads();

    // 2. segment-local scan (zero init), 4 segs x 64 complex cols
    const int pl = t & 63, seg = t >> 6;
    const int pg = (n0 >> 1) + pl;
    const float lr = g_lam_re[pg], li = g_lam_im[pg];
    {
        float yr = 0.f, yi = 0.f;
        float* colp = Stile + 2 * pl;
#pragma unroll 4
        for (int tt = 0; tt < 32; ++tt) {
            int row = seg * 32 + tt;
            float2 s = *(float2*)(colp + row * 130);
            float nyr = fmaf(lr, yr, fmaf(-li, yi, s.x));
            float nyi = fmaf(lr, yi, fmaf( li, yr, s.y));
            yr = nyr; yi = nyi;
            *(float2*)(colp + row * 130) = make_float2(yr, yi);
        }
        carrR[seg * 64 + pl] = yr;
        carrI[seg * 64 + pl] = yi;
    }
    __syncthreads();

    // 3. seg-carry combine (lam^32) -> chunk aggregate; publish (release);
    //    lookback: fold predecessors' aggregates into E_chunk (acquire).
    if (t < 64) {
        int pg2 = (n0 >> 1) + t;
        float l32r = g_lam32_re[pg2], l32i = g_lam32_im[pg2];
        float Pr = 0.f, Pi = 0.f;
        float sp[4][2];
#pragma unroll
        for (int q = 0; q < 4; ++q) {
            sp[q][0] = Pr; sp[q][1] = Pi;
            float cr = carrR[q * 64 + t], ci = carrI[q * 64 + t];
            float nPr = fmaf(l32r, Pr, fmaf(-l32i, Pi, cr));
            float nPi = fmaf(l32r, Pi, fmaf( l32i, Pr, ci));
            Pr = nPr; Pi = nPi;
        }
        // publish chunk aggregate
        size_t ci0 = (size_t)(bIdx * NCH + cIdx) * PDIM + pg2;
        *(float2*)(g_car + 2 * ci0) = make_float2(Pr, Pi);
        st_release_u32(g_flag + ci0, 1u);

        // lookback over earlier chunks (independent aggregates, no chaining)
        float Ecr = 0.f, Eci = 0.f;
        for (int j = 0; j < cIdx; ++j) {
            int d = cIdx - 1 - j;
            size_t fj = (size_t)(bIdx * NCH + j) * PDIM + pg2;
            while (ld_acquire_u32(g_flag + fj) == 0) { }
            float2 cv = ld_relaxed_f2(g_car + 2 * fj);
            float pr = g_powT_re[d][pg2], pi = g_powT_im[d][pg2];
            Ecr = fmaf(pr, cv.x, fmaf(-pi, cv.y, Ecr));
            Eci = fmaf(pr, cv.y, fmaf( pi, cv.x, Eci));
        }
#pragma unroll
        for (int q = 0; q < 4; ++q) {   // seg prefixes now include E_chunk later
            prefR[q * 64 + t] = sp[q][0];
            prefI[q * 64 + t] = sp[q][1];
        }
        carrR[t] = Ecr;   // reuse smem for E_chunk
        carrI[t] = Eci;
    }
    __syncthreads();

    // 4. total prefix apply + fp16 convert, write final states to g_S16
    {
        float Ecr = carrR[pl], Eci = carrI[pl];
        float p32r = g_pow32_re[seg][pg], p32i = g_pow32_im[seg][pg];
        float Er = prefR[seg * 64 + pl] + p32r * Ecr - p32i * Eci;
        float Ei = prefI[seg * 64 + pl] + p32r * Eci + p32i * Ecr;
        float inv = g_inv_scl[pg];
        float wr = lr, wi = li;
        float* colp = Stile + 2 * pl;
        __half2* op = (__half2*)g_S16 + (size_t)m0 * PDIM + pg;
#pragma unroll 4
        for (int tt = 0; tt < 32; ++tt) {
            int row = seg * 32 + tt;
            float2 s = *(float2*)(colp + row * 130);
            float xr = fmaf(wr, Er, fmaf(-wi, Ei, s.x));
            float xi = fmaf(wr, Ei, fmaf( wi, Er, s.y));
            op[(size_t)row * PDIM] = __floats2half2_rn(xr * inv, xi * inv);
            float nwr = fmaf(wr, lr, -wi * li);
            float nwi = fmaf(wr, li,  wi * lr);
            wr = nwr; wi = nwi;
        }
    }
}

// ---------------------------------------------------------------------------
// GEMM3: C = S16 @ Wc16^T + D*u.  cp.async 4-stage pipeline, fused epilogue.
// ---------------------------------------------------------------------------
#define G3_SMEM 65536

__global__ void __launch_bounds__(256)
s5_gemm3(float* __restrict__ C,
         const float* __restrict__ Dvec,
         const float* __restrict__ U)
{
    extern __shared__ char sm[];
    uint32_t sb = smem_u32(sm);

    const int t = threadIdx.x;
    const int lane = t & 31, w = t >> 5;
    const int g = lane >> 2, tig = lane & 3;
    const int mBase = (w & 3) * 32;
    const int nBase = (w >> 2) * 64;
    const int m0 = blockIdx.y * 128, n0 = blockIdx.x * 128;

    const int r0 = t >> 2, c0 = t & 3;
    const uint32_t sAoff = r0 * 64 + (((uint32_t)(c0 ^ ((r0 >> 1) & 3))) << 4);
    const __half* Ag = g_S16 + (size_t)(m0 + r0) * K3 + c0 * 8;
    const __half* Bg = g_Wc16 + (size_t)(n0 + r0) * K3 + c0 * 8;

    auto issue = [&](int slot, int kof) {
        uint32_t base = sb + slot * 16384;
        cp_async16(base + sAoff,        Ag + kof);
        cp_async16(base + sAoff + 4096, Ag + kof + (size_t)64 * K3);
        cp_async16(base + sAoff + 8192, Bg + kof);
        cp_async16(base + sAoff + 12288,Bg + kof + (size_t)64 * K3);
    };

    float acc[2][8][4];
#pragma unroll
    for (int mi = 0; mi < 2; ++mi)
#pragma unroll
        for (int ni = 0; ni < 8; ++ni)
#pragma unroll
            for (int q = 0; q < 4; ++q) acc[mi][ni][q] = 0.0f;

    issue(0, 0);  CP_COMMIT();
    issue(1, 32); CP_COMMIT();
    issue(2, 64); CP_COMMIT();

    const int NIT = K3 / 32;   // 16
    for (int it = 0; it < NIT; ++it) {
        CP_WAIT(2);
        __syncthreads();
        uint32_t stg = sb + (it & 3) * 16384;
        MMA_STAGE(stg);
        if (it + 3 < NIT) issue((it + 3) & 3, (it + 3) * 32);
        CP_COMMIT();
    }

    // Epilogue with D*u feedthrough
#pragma unroll
    for (int mi = 0; mi < 2; ++mi) {
        int row0 = m0 + mBase + mi * 16 + g;
#pragma unroll
        for (int ni = 0; ni < 8; ++ni) {
            int col = n0 + nBase + ni * 8 + 2 * tig;
            float d0 = Dvec[col], d1 = Dvec[col + 1];
            float2 u0 = *(const float2*)(U + (size_t)row0 * HDIM + col);
            float2 u1 = *(const float2*)(U + (size_t)(row0 + 8) * HDIM + col);
            float2 v0 = make_float2(fmaf(d0, u0.x, acc[mi][ni][0]),
                                    fmaf(d1, u0.y, acc[mi][ni][1]));
            float2 v1 = make_float2(fmaf(d0, u1.x, acc[mi][ni][2]),
                                    fmaf(d1, u1.y, acc[mi][ni][3]));
            *(float2*)(C + (size_t)row0 * N3 + col) = v0;
            *(float2*)(C + (size_t)(row0 + 8) * N3 + col) = v1;
        }
    }
}

// ---------------------------------------------------------------------------
extern "C" void kernel_launch(void* const* d_in, const int* in_sizes, int n_in,
                              void* d_out, int out_size)
{
    const float* u   = (const float*)d_in[0];
    const float* Lre = (const float*)d_in[1];
    const float* Lim = (const float*)d_in[2];
    const float* Bp  = (const float*)d_in[3];
    const float* Cp  = (const float*)d_in[4];
    const float* Dv  = (const float*)d_in[5];
    const float* lst = (const float*)d_in[6];
    float* out = (float*)d_out;

    cudaFuncSetAttribute(s5_gemm1_scan,
                         cudaFuncAttributeMaxDynamicSharedMemorySize, G1_SMEM);
    cudaFuncSetAttribute(s5_gemm3,
                         cudaFuncAttributeMaxDynamicSharedMemorySize, G3_SMEM);

    // 1. discretize + pack fp16 weights + power tables;  u->fp16 + flag clear
    s5_setup_kernel<<<PDIM, HDIM>>>(Lre, Lim, Bp, Cp, lst);
    s5_u2h_kernel<<<(MROWS * HDIM) / 2048, 256>>>(u);

    // 2. Bu GEMM + fused full scan (lookback) -> final states fp16 (g_S16)
    s5_gemm1_scan<<<dim3(N1 / 128, MROWS / 128), 256, G1_SMEM>>>();

    // 3. y = states16 @ Wc16^T + D*u
    s5_gemm3<<<dim3(N3 / 128, MROWS / 128), 256, G3_SMEM>>>(out, Dv, u);
}